// round 1
// baseline (speedup 1.0000x reference)
#include <cuda_runtime.h>
#include <mma.h>
#include <cstdint>
#include <cstddef>

using namespace nvcuda;

// Problem constants (fixed shapes for this dataset)
#define NBATCH   2
#define CH       64
#define NPTS     262144
#define NBLK     2

// Tiling
#define TILE     192          // output positions per CTA
#define ROWS     210          // smem rows per activation buffer (covers halo + wmma padding)
#define LDS      68           // padded row pitch (floats) to reduce smem bank conflicts
#define NTHREADS 256

// Scratch (device globals: allocation-free)
__device__ float g_mid[(size_t)NBATCH * NPTS * CH];   // inter-block activations (128 MB)
__device__ float g_wt[NBLK * 3 * 3 * CH * CH];        // repacked weights [bl(6)][tap(3)][i][o], BN-scaled, tf32-rounded
__device__ float g_bias[NBLK * 3 * CH];               // BN affine bias per (bl, layer, o)
__device__ int   g_is64;                              // 1 if permutation arrays are int64, 0 if int32

// ---------------------------------------------------------------------------
// Detect index dtype: if int64, the high 32-bit word of every element is 0.
// For int32 permutations, the odd words are distinct indices (can't all be 0).
// ---------------------------------------------------------------------------
__global__ void detect_idx_kernel(const unsigned int* __restrict__ w) {
    __shared__ int any;
    if (threadIdx.x == 0) any = 0;
    __syncthreads();
    int local = 0;
    for (int i = threadIdx.x; i < 2048; i += blockDim.x)
        if (w[2 * i + 1] != 0u) local = 1;
    if (local) atomicOr(&any, 1);
    __syncthreads();
    if (threadIdx.x == 0) g_is64 = any ? 0 : 1;
}

// ---------------------------------------------------------------------------
// Repack conv weights: fold BN scale, transpose to [bl][tap][i][o], round tf32.
// conv_w: [blk][layer][O][I][K=3], bn arrays: [blk][layer][C]
// ---------------------------------------------------------------------------
__global__ void repack_kernel(const float* __restrict__ w,
                              const float* __restrict__ gm,
                              const float* __restrict__ bt,
                              const float* __restrict__ mn,
                              const float* __restrict__ vr) {
    int idx = blockIdx.x * blockDim.x + threadIdx.x;
    if (idx >= NBLK * 3 * CH * CH) return;
    int o  = idx & 63;
    int i  = (idx >> 6) & 63;
    int bl = idx >> 12;                  // 0..5 = blk*3 + layer
    float scale = gm[bl * CH + o] * rsqrtf(vr[bl * CH + o] + 1e-5f);
#pragma unroll
    for (int t = 0; t < 3; t++) {
        float val = w[(((size_t)bl * CH + o) * CH + i) * 3 + t] * scale;
        g_wt[(size_t)(bl * 3 + t) * (CH * CH) + i * CH + o] = wmma::__float_to_tf32(val);
    }
    if (i == 0)
        g_bias[bl * CH + o] = bt[bl * CH + o] - mn[bl * CH + o] * scale;
}

// ---------------------------------------------------------------------------
// One conv layer over the CTA tile: sOut[r,:] = sum_{tap,i} sIn[r+tap,i]*W[tap,i,:]
// wmma m16n16k8 tf32, 2 N-tiles per task for tensor-pipe ILP.
// ---------------------------------------------------------------------------
__device__ __forceinline__ void conv_pass(const float* __restrict__ sIn,
                                          float* __restrict__ sOut,
                                          const float* __restrict__ sW,
                                          int mTiles, int warp) {
    for (int task = warp; task < mTiles * 2; task += (NTHREADS / 32)) {
        int mt  = task >> 1;
        int nt0 = (task & 1) * 2;
        wmma::fragment<wmma::accumulator, 16, 16, 8, float> acc0, acc1;
        wmma::fill_fragment(acc0, 0.f);
        wmma::fill_fragment(acc1, 0.f);
#pragma unroll
        for (int tap = 0; tap < 3; tap++) {
#pragma unroll
            for (int ks = 0; ks < 8; ks++) {
                wmma::fragment<wmma::matrix_a, 16, 16, 8, wmma::precision::tf32, wmma::row_major> af;
                wmma::fragment<wmma::matrix_b, 16, 16, 8, wmma::precision::tf32, wmma::row_major> bf0, bf1;
                wmma::load_matrix_sync(af, sIn + (mt * 16 + tap) * LDS + ks * 8, LDS);
                wmma::load_matrix_sync(bf0, sW + (tap * 64 + ks * 8) * LDS + nt0 * 16, LDS);
                wmma::load_matrix_sync(bf1, sW + (tap * 64 + ks * 8) * LDS + (nt0 + 1) * 16, LDS);
                wmma::mma_sync(acc0, af, bf0, acc0);
                wmma::mma_sync(acc1, af, bf1, acc1);
            }
        }
        wmma::store_matrix_sync(sOut + mt * 16 * LDS + nt0 * 16, acc0, LDS, wmma::mem_row_major);
        wmma::store_matrix_sync(sOut + mt * 16 * LDS + (nt0 + 1) * 16, acc1, LDS, wmma::mem_row_major);
    }
}

// ---------------------------------------------------------------------------
// Fused block kernel: gather(pa) -> conv-bn-relu x2 -> conv-bn -> relu(x+h) -> scatter(pa)
// ---------------------------------------------------------------------------
__global__ __launch_bounds__(NTHREADS)
void block_kernel(const float* __restrict__ xin, float* __restrict__ xout,
                  const void* __restrict__ paPtr,
                  const float* __restrict__ wt, const float* __restrict__ bias) {
    extern __shared__ float smem[];
    float* sA    = smem;                       // input (gathered), 210 x LDS
    float* sB    = sA + ROWS * LDS;            // conv1 out / conv3 out
    float* sC    = sB + ROWS * LDS;            // conv2 out
    float* sW    = sC + ROWS * LDS;            // current layer weights, 192 x LDS
    float* sBias = sW + 192 * LDS;             // 3 x 64
    int*   sIdx  = (int*)(sBias + 192);        // 210 gathered source indices

    const int tid   = threadIdx.x;
    const int warp  = tid >> 5;
    const int tile0 = blockIdx.x * TILE;
    const int b     = blockIdx.y;
    const int is64  = g_is64;

    // --- permutation indices (row r <-> global gathered pos tile0-3+r) ---
    for (int r = tid; r < ROWS; r += NTHREADS) {
        int p = tile0 - 3 + r;
        int v = -1;
        if (p >= 0 && p < NPTS && r < TILE + 6) {
            size_t gp = (size_t)b * NPTS + p;
            v = is64 ? (int)((const long long*)paPtr)[gp] : ((const int*)paPtr)[gp];
        }
        sIdx[r] = v;
    }
    if (tid < 3 * CH) sBias[tid] = bias[tid];
    __syncthreads();

    // --- gather input rows into sA (zero for out-of-range halo) ---
    for (int it = tid; it < ROWS * 16; it += NTHREADS) {
        int r = it >> 4, c4 = it & 15;
        int src = sIdx[r];
        float4 v = make_float4(0.f, 0.f, 0.f, 0.f);
        if (src >= 0)
            v = *(const float4*)(xin + ((size_t)b * NPTS + src) * CH + c4 * 4);
        *(float4*)(sA + r * LDS + c4 * 4) = v;
    }
    // --- layer 0 weights ---
    for (int it = tid; it < 192 * 16; it += NTHREADS) {
        int rr = it >> 4, c4 = it & 15;
        *(float4*)(sW + rr * LDS + c4 * 4) = *(const float4*)(wt + rr * 64 + c4 * 4);
    }
    __syncthreads();

    // conv1: sA -> sB (rows 0..207 computed; pos = tile0-2+r)
    conv_pass(sA, sB, sW, 13, warp);
    __syncthreads();

    // fixup B (bias0 + relu, zero invalid) + stage layer 1 weights
    for (int it = tid; it < ROWS * 16; it += NTHREADS) {
        int r = it >> 4, c4 = it & 15;
        int p = tile0 - 2 + r;
        float4 v = *(float4*)(sB + r * LDS + c4 * 4);
        float4 bb = *(float4*)(sBias + c4 * 4);
        if (r < TILE + 4 && p >= 0 && p < NPTS) {
            v.x = fmaxf(v.x + bb.x, 0.f); v.y = fmaxf(v.y + bb.y, 0.f);
            v.z = fmaxf(v.z + bb.z, 0.f); v.w = fmaxf(v.w + bb.w, 0.f);
        } else {
            v = make_float4(0.f, 0.f, 0.f, 0.f);
        }
        *(float4*)(sB + r * LDS + c4 * 4) = v;
    }
    for (int it = tid; it < 192 * 16; it += NTHREADS) {
        int rr = it >> 4, c4 = it & 15;
        *(float4*)(sW + rr * LDS + c4 * 4) = *(const float4*)(wt + 3 * 4096 + rr * 64 + c4 * 4);
    }
    __syncthreads();

    // conv2: sB -> sC (pos = tile0-1+r)
    conv_pass(sB, sC, sW, 13, warp);
    __syncthreads();

    // fixup C (bias1 + relu, zero invalid) + stage layer 2 weights
    for (int it = tid; it < ROWS * 16; it += NTHREADS) {
        int r = it >> 4, c4 = it & 15;
        int p = tile0 - 1 + r;
        float4 v = *(float4*)(sC + r * LDS + c4 * 4);
        float4 bb = *(float4*)(sBias + 64 + c4 * 4);
        if (r < TILE + 2 && p >= 0 && p < NPTS) {
            v.x = fmaxf(v.x + bb.x, 0.f); v.y = fmaxf(v.y + bb.y, 0.f);
            v.z = fmaxf(v.z + bb.z, 0.f); v.w = fmaxf(v.w + bb.w, 0.f);
        } else {
            v = make_float4(0.f, 0.f, 0.f, 0.f);
        }
        *(float4*)(sC + r * LDS + c4 * 4) = v;
    }
    for (int it = tid; it < 192 * 16; it += NTHREADS) {
        int rr = it >> 4, c4 = it & 15;
        *(float4*)(sW + rr * LDS + c4 * 4) = *(const float4*)(wt + 6 * 4096 + rr * 64 + c4 * 4);
    }
    __syncthreads();

    // conv3: sC -> sB (rows 0..191; pos = tile0+r)
    conv_pass(sC, sB, sW, 12, warp);
    __syncthreads();

    // epilogue: relu(residual + conv3 + bias2), scatter out[pa[p]] = y[p]
    for (int it = tid; it < TILE * 16; it += NTHREADS) {
        int r = it >> 4, c4 = it & 15;
        int p = tile0 + r;
        if (p >= NPTS) continue;
        int dst = sIdx[r + 3];  // = pa[p]
        float4 h  = *(float4*)(sB + r * LDS + c4 * 4);
        float4 a  = *(float4*)(sA + (r + 3) * LDS + c4 * 4);
        float4 bb = *(float4*)(sBias + 128 + c4 * 4);
        float4 y;
        y.x = fmaxf(a.x + h.x + bb.x, 0.f);
        y.y = fmaxf(a.y + h.y + bb.y, 0.f);
        y.z = fmaxf(a.z + h.z + bb.z, 0.f);
        y.w = fmaxf(a.w + h.w + bb.w, 0.f);
        *(float4*)(xout + ((size_t)b * NPTS + dst) * CH + c4 * 4) = y;
    }
}

// ---------------------------------------------------------------------------
// Launch
// ---------------------------------------------------------------------------
extern "C" void kernel_launch(void* const* d_in, const int* in_sizes, int n_in,
                              void* d_out, int out_size) {
    const float* x      = (const float*)d_in[0];
    const void*  pa1    = d_in[1];
    const void*  pa2    = d_in[3];
    const float* conv_w = (const float*)d_in[5];
    const float* gma    = (const float*)d_in[6];
    const float* bta    = (const float*)d_in[7];
    const float* mean   = (const float*)d_in[8];
    const float* var    = (const float*)d_in[9];

    float* mid;  cudaGetSymbolAddress((void**)&mid,  g_mid);
    float* wt;   cudaGetSymbolAddress((void**)&wt,   g_wt);
    float* bias; cudaGetSymbolAddress((void**)&bias, g_bias);

    const int smemBytes = (3 * ROWS * LDS + 192 * LDS + 192) * 4 + ROWS * 4;
    cudaFuncSetAttribute(block_kernel, cudaFuncAttributeMaxDynamicSharedMemorySize, smemBytes);

    detect_idx_kernel<<<1, 256>>>((const unsigned int*)pa1);
    repack_kernel<<<(NBLK * 3 * CH * CH + 255) / 256, 256>>>(conv_w, gma, bta, mean, var);

    dim3 grid((NPTS + TILE - 1) / TILE, NBATCH);
    // block 0: x -> g_mid (perm1, weight/bias slab 0)
    block_kernel<<<grid, NTHREADS, smemBytes>>>(x, mid, pa1, wt, bias);
    // block 1: g_mid -> d_out (perm2, weight/bias slab 1)
    block_kernel<<<grid, NTHREADS, smemBytes>>>(mid, (float*)d_out, pa2,
                                                wt + 3 * 3 * CH * CH, bias + 3 * CH);
}

// round 2
// speedup vs baseline: 1.3366x; 1.3366x over previous
#include <cuda_runtime.h>
#include <mma.h>
#include <cstdint>
#include <cstddef>

using namespace nvcuda;

// Problem constants (fixed shapes for this dataset)
#define NBATCH   2
#define CH       64
#define NPTS     262144
#define NBLK     2

// Tiling
#define TILE     192          // output positions per CTA
#define ROWS     210          // smem rows per activation buffer (covers halo + wmma padding)
#define LDS      68           // padded row pitch (floats) to reduce smem bank conflicts
#define NTHREADS 512
#define NWARP    (NTHREADS / 32)

// Scratch (device globals: allocation-free)
__device__ float g_mid[(size_t)NBATCH * NPTS * CH];   // inter-block activations (128 MB)
__device__ float g_wt[NBLK * 3 * 3 * CH * CH];        // repacked weights [bl(6)][tap(3)][i][o], BN-scaled, tf32-rounded
__device__ float g_bias[NBLK * 3 * CH];               // BN affine bias per (bl, layer, o)
__device__ int   g_is64;                              // 1 if permutation arrays are int64, 0 if int32

// ---------------------------------------------------------------------------
// Detect index dtype: if int64, the high 32-bit word of every element is 0.
// ---------------------------------------------------------------------------
__global__ void detect_idx_kernel(const unsigned int* __restrict__ w) {
    __shared__ int any;
    if (threadIdx.x == 0) any = 0;
    __syncthreads();
    int local = 0;
    for (int i = threadIdx.x; i < 2048; i += blockDim.x)
        if (w[2 * i + 1] != 0u) local = 1;
    if (local) atomicOr(&any, 1);
    __syncthreads();
    if (threadIdx.x == 0) g_is64 = any ? 0 : 1;
}

// ---------------------------------------------------------------------------
// Repack conv weights: fold BN scale, transpose to [bl][tap][i][o], round tf32.
// ---------------------------------------------------------------------------
__global__ void repack_kernel(const float* __restrict__ w,
                              const float* __restrict__ gm,
                              const float* __restrict__ bt,
                              const float* __restrict__ mn,
                              const float* __restrict__ vr) {
    int idx = blockIdx.x * blockDim.x + threadIdx.x;
    if (idx >= NBLK * 3 * CH * CH) return;
    int o  = idx & 63;
    int i  = (idx >> 6) & 63;
    int bl = idx >> 12;                  // 0..5 = blk*3 + layer
    float scale = gm[bl * CH + o] * rsqrtf(vr[bl * CH + o] + 1e-5f);
#pragma unroll
    for (int t = 0; t < 3; t++) {
        float val = w[(((size_t)bl * CH + o) * CH + i) * 3 + t] * scale;
        g_wt[(size_t)(bl * 3 + t) * (CH * CH) + i * CH + o] = wmma::__float_to_tf32(val);
    }
    if (i == 0)
        g_bias[bl * CH + o] = bt[bl * CH + o] - mn[bl * CH + o] * scale;
}

// ---------------------------------------------------------------------------
// One conv layer over the CTA tile. Warp owns one 16-row m-tile, computes all
// 64 output channels (4 accumulators). Optional warp-local fixup applies
// bias+relu (or zero for out-of-range positions) to the warp's own tile.
// ---------------------------------------------------------------------------
__device__ __forceinline__ void conv_pass(const float* __restrict__ sIn,
                                          float* __restrict__ sOut,
                                          const float* __restrict__ sW,
                                          int mTiles, int warp, int lane,
                                          const float* __restrict__ sBiasL,
                                          int pbase, bool doFix) {
    for (int mt = warp; mt < mTiles; mt += NWARP) {
        wmma::fragment<wmma::accumulator, 16, 16, 8, float> acc[4];
#pragma unroll
        for (int i = 0; i < 4; i++) wmma::fill_fragment(acc[i], 0.f);
#pragma unroll
        for (int tap = 0; tap < 3; tap++) {
#pragma unroll
            for (int ks = 0; ks < 8; ks++) {
                wmma::fragment<wmma::matrix_a, 16, 16, 8, wmma::precision::tf32, wmma::row_major> af;
                wmma::load_matrix_sync(af, sIn + (mt * 16 + tap) * LDS + ks * 8, LDS);
#pragma unroll
                for (int nt = 0; nt < 4; nt++) {
                    wmma::fragment<wmma::matrix_b, 16, 16, 8, wmma::precision::tf32, wmma::row_major> bf;
                    wmma::load_matrix_sync(bf, sW + (tap * 64 + ks * 8) * LDS + nt * 16, LDS);
                    wmma::mma_sync(acc[nt], af, bf, acc[nt]);
                }
            }
        }
#pragma unroll
        for (int nt = 0; nt < 4; nt++)
            wmma::store_matrix_sync(sOut + mt * 16 * LDS + nt * 16, acc[nt], LDS, wmma::mem_row_major);

        if (doFix) {
            __syncwarp();
            // 2 lanes per row: lane>>1 = row-in-tile, lane&1 = column half (32 floats)
            int r = mt * 16 + (lane >> 1);
            int p = pbase + r;
            bool valid = (p >= 0) && (p < NPTS);
            float* rowp = sOut + r * LDS + (lane & 1) * 32;
            const float* bp = sBiasL + (lane & 1) * 32;
#pragma unroll
            for (int j = 0; j < 8; j++) {
                float4 v = *(float4*)(rowp + j * 4);
                if (valid) {
                    float4 bb = *(const float4*)(bp + j * 4);
                    v.x = fmaxf(v.x + bb.x, 0.f); v.y = fmaxf(v.y + bb.y, 0.f);
                    v.z = fmaxf(v.z + bb.z, 0.f); v.w = fmaxf(v.w + bb.w, 0.f);
                } else {
                    v = make_float4(0.f, 0.f, 0.f, 0.f);
                }
                *(float4*)(rowp + j * 4) = v;
            }
        }
    }
}

// ---------------------------------------------------------------------------
// Fused block kernel: gather(pa) -> conv-bn-relu x2 -> conv-bn -> relu(x+h) -> scatter(pa)
// ---------------------------------------------------------------------------
__global__ __launch_bounds__(NTHREADS, 1)
void block_kernel(const float* __restrict__ xin, float* __restrict__ xout,
                  const void* __restrict__ paPtr,
                  const float* __restrict__ wt, const float* __restrict__ bias) {
    extern __shared__ float smem[];
    float* sA    = smem;                       // input (gathered), ROWS x LDS
    float* sB    = sA + ROWS * LDS;            // conv1 out / conv3 out
    float* sC    = sB + ROWS * LDS;            // conv2 out
    float* sW    = sC + ROWS * LDS;            // current layer weights, 192 x LDS
    float* sBias = sW + 192 * LDS;             // 3 x 64
    int*   sIdx  = (int*)(sBias + 192);        // gathered source indices

    const int tid   = threadIdx.x;
    const int warp  = tid >> 5;
    const int lane  = tid & 31;
    const int tile0 = blockIdx.x * TILE;
    const int b     = blockIdx.y;
    const int is64  = g_is64;

    // --- permutation indices (row r <-> global gathered pos tile0-3+r) ---
    for (int r = tid; r < TILE + 6; r += NTHREADS) {
        int p = tile0 - 3 + r;
        int v = -1;
        if (p >= 0 && p < NPTS) {
            size_t gp = (size_t)b * NPTS + p;
            v = is64 ? (int)((const long long*)paPtr)[gp] : ((const int*)paPtr)[gp];
        }
        sIdx[r] = v;
    }
    if (tid < 3 * CH) sBias[tid] = bias[tid];
    __syncthreads();

    // --- gather input rows into sA (zero for out-of-range halo) + layer0 W ---
    for (int it = tid; it < (TILE + 6) * 16; it += NTHREADS) {
        int r = it >> 4, c4 = it & 15;
        int src = sIdx[r];
        float4 v = make_float4(0.f, 0.f, 0.f, 0.f);
        if (src >= 0)
            v = *(const float4*)(xin + ((size_t)b * NPTS + src) * CH + c4 * 4);
        *(float4*)(sA + r * LDS + c4 * 4) = v;
    }
    for (int it = tid; it < 192 * 16; it += NTHREADS) {
        int rr = it >> 4, c4 = it & 15;
        *(float4*)(sW + rr * LDS + c4 * 4) = *(const float4*)(wt + rr * 64 + c4 * 4);
    }
    __syncthreads();

    // conv1: sA -> sB (rows 0..207; pos = tile0-2+r), fixup bias0+relu inline
    conv_pass(sA, sB, sW, 13, warp, lane, sBias, tile0 - 2, true);
    __syncthreads();

    // stage layer 1 weights
    for (int it = tid; it < 192 * 16; it += NTHREADS) {
        int rr = it >> 4, c4 = it & 15;
        *(float4*)(sW + rr * LDS + c4 * 4) = *(const float4*)(wt + 3 * 4096 + rr * 64 + c4 * 4);
    }
    __syncthreads();

    // conv2: sB -> sC (pos = tile0-1+r), fixup bias1+relu inline
    conv_pass(sB, sC, sW, 13, warp, lane, sBias + 64, tile0 - 1, true);
    __syncthreads();

    // stage layer 2 weights
    for (int it = tid; it < 192 * 16; it += NTHREADS) {
        int rr = it >> 4, c4 = it & 15;
        *(float4*)(sW + rr * LDS + c4 * 4) = *(const float4*)(wt + 6 * 4096 + rr * 64 + c4 * 4);
    }
    __syncthreads();

    // conv3: sC -> sB (rows 0..191; pos = tile0+r), no fixup (epilogue owns it)
    conv_pass(sC, sB, sW, 12, warp, lane, nullptr, 0, false);
    __syncthreads();

    // epilogue: relu(residual + conv3 + bias2), scatter out[pa[p]] = y[p]
    for (int it = tid; it < TILE * 16; it += NTHREADS) {
        int r = it >> 4, c4 = it & 15;
        int p = tile0 + r;
        if (p >= NPTS) continue;
        int dst = sIdx[r + 3];  // = pa[p]
        float4 h  = *(float4*)(sB + r * LDS + c4 * 4);
        float4 a  = *(float4*)(sA + (r + 3) * LDS + c4 * 4);
        float4 bb = *(float4*)(sBias + 128 + c4 * 4);
        float4 y;
        y.x = fmaxf(a.x + h.x + bb.x, 0.f);
        y.y = fmaxf(a.y + h.y + bb.y, 0.f);
        y.z = fmaxf(a.z + h.z + bb.z, 0.f);
        y.w = fmaxf(a.w + h.w + bb.w, 0.f);
        *(float4*)(xout + ((size_t)b * NPTS + dst) * CH + c4 * 4) = y;
    }
}

// ---------------------------------------------------------------------------
// Launch
// ---------------------------------------------------------------------------
extern "C" void kernel_launch(void* const* d_in, const int* in_sizes, int n_in,
                              void* d_out, int out_size) {
    const float* x      = (const float*)d_in[0];
    const void*  pa1    = d_in[1];
    const void*  pa2    = d_in[3];
    const float* conv_w = (const float*)d_in[5];
    const float* gma    = (const float*)d_in[6];
    const float* bta    = (const float*)d_in[7];
    const float* mean   = (const float*)d_in[8];
    const float* var    = (const float*)d_in[9];

    float* mid;  cudaGetSymbolAddress((void**)&mid,  g_mid);
    float* wt;   cudaGetSymbolAddress((void**)&wt,   g_wt);
    float* bias; cudaGetSymbolAddress((void**)&bias, g_bias);

    const int smemBytes = (3 * ROWS * LDS + 192 * LDS + 192) * 4 + ROWS * 4;
    cudaFuncSetAttribute(block_kernel, cudaFuncAttributeMaxDynamicSharedMemorySize, smemBytes);

    detect_idx_kernel<<<1, 256>>>((const unsigned int*)pa1);
    repack_kernel<<<(NBLK * 3 * CH * CH + 255) / 256, 256>>>(conv_w, gma, bta, mean, var);

    dim3 grid((NPTS + TILE - 1) / TILE, NBATCH);
    // block 0: x -> g_mid (perm1, weight/bias slab 0)
    block_kernel<<<grid, NTHREADS, smemBytes>>>(x, mid, pa1, wt, bias);
    // block 1: g_mid -> d_out (perm2, weight/bias slab 1)
    block_kernel<<<grid, NTHREADS, smemBytes>>>(mid, (float*)d_out, pa2,
                                                wt + 3 * 3 * CH * CH, bias + 3 * CH);
}

// round 3
// speedup vs baseline: 1.7703x; 1.3245x over previous
#include <cuda_runtime.h>
#include <mma.h>
#include <cstdint>
#include <cstddef>

using namespace nvcuda;

// Problem constants (fixed shapes for this dataset)
#define NBATCH   2
#define CH       64
#define NPTS     262144
#define NBLK     2

// Tiling
#define TILE     192          // output positions per CTA
#define ROWS     210          // smem rows per activation buffer (halo + wmma padding)
#define LDS      68           // padded row pitch (floats)
#define NTHREADS 416          // 13 warps: matches 13 m-tiles; reg cap 157/thread
#define NWARP    13

// Scratch (device globals: allocation-free)
__device__ float g_mid[(size_t)NBATCH * NPTS * CH];   // inter-block activations (128 MB)
__device__ float g_wt[NBLK * 3 * 3 * CH * CH];        // repacked weights [bl(6)][tap][i][o], BN-scaled, tf32
__device__ float g_bias[NBLK * 3 * CH];               // BN affine bias per (bl, layer, o)
__device__ float g_wfrag[NBLK * 3 * 3 * 8 * 4 * 128]; // B-fragments in per-lane register order
__device__ int   g_is64;                              // 1 if permutation arrays are int64

// ---------------------------------------------------------------------------
// Detect index dtype: int64 permutations have all-zero high words.
// ---------------------------------------------------------------------------
__global__ void detect_idx_kernel(const unsigned int* __restrict__ w) {
    __shared__ int any;
    if (threadIdx.x == 0) any = 0;
    __syncthreads();
    int local = 0;
    for (int i = threadIdx.x; i < 2048; i += blockDim.x)
        if (w[2 * i + 1] != 0u) local = 1;
    if (local) atomicOr(&any, 1);
    __syncthreads();
    if (threadIdx.x == 0) g_is64 = any ? 0 : 1;
}

// ---------------------------------------------------------------------------
// Repack conv weights: fold BN scale, transpose to [bl][tap][i][o], tf32 round.
// ---------------------------------------------------------------------------
__global__ void repack_kernel(const float* __restrict__ w,
                              const float* __restrict__ gm,
                              const float* __restrict__ bt,
                              const float* __restrict__ mn,
                              const float* __restrict__ vr) {
    int idx = blockIdx.x * blockDim.x + threadIdx.x;
    if (idx >= NBLK * 3 * CH * CH) return;
    int o  = idx & 63;
    int i  = (idx >> 6) & 63;
    int bl = idx >> 12;                  // 0..5 = blk*3 + layer
    float scale = gm[bl * CH + o] * rsqrtf(vr[bl * CH + o] + 1e-5f);
#pragma unroll
    for (int t = 0; t < 3; t++) {
        float val = w[(((size_t)bl * CH + o) * CH + i) * 3 + t] * scale;
        g_wt[(size_t)(bl * 3 + t) * (CH * CH) + i * CH + o] = wmma::__float_to_tf32(val);
    }
    if (i == 0)
        g_bias[bl * CH + o] = bt[bl * CH + o] - mn[bl * CH + o] * scale;
}

// ---------------------------------------------------------------------------
// Pre-arrange B fragments in per-lane register order.
// One warp per (bl, tap, ks, nt): load the 8x16 tf32 B tile via wmma, then dump
// each lane's fragment registers contiguously. Conv kernel reloads each
// fragment with a single conflict-free LDS.128.
// ---------------------------------------------------------------------------
__global__ void prep_frag_kernel() {
    int w = (blockIdx.x * blockDim.x + threadIdx.x) >> 5;
    int lane = threadIdx.x & 31;
    if (w >= NBLK * 3 * 3 * 8 * 4) return;
    int nt = w & 3;
    int t1 = w >> 2;
    int ks = t1 & 7;
    t1 >>= 3;
    int tap = t1 % 3;
    int bl  = t1 / 3;

    wmma::fragment<wmma::matrix_b, 16, 16, 8, wmma::precision::tf32, wmma::row_major> bf;
    const float* src = g_wt + (size_t)(bl * 3 + tap) * (CH * CH) + ks * 8 * CH + nt * 16;
    wmma::load_matrix_sync(bf, src, CH);

    float* dst = g_wfrag + (size_t)w * 128 + lane * 4;
#pragma unroll
    for (int e = 0; e < bf.num_elements; e++) dst[e] = bf.x[e];
}

// ---------------------------------------------------------------------------
// One conv layer over the CTA tile. Warp owns one 16-row m-tile, 4 accs (N=64).
// B fragments come from fragment-order smem via one float4 load each.
// ---------------------------------------------------------------------------
__device__ __forceinline__ void conv_pass(const float* __restrict__ sIn,
                                          float* __restrict__ sOut,
                                          const float* __restrict__ sW,
                                          int mTiles, int warp, int lane,
                                          const float* __restrict__ sBiasL,
                                          int pbase, bool doFix) {
    for (int mt = warp; mt < mTiles; mt += NWARP) {
        wmma::fragment<wmma::accumulator, 16, 16, 8, float> acc[4];
#pragma unroll
        for (int i = 0; i < 4; i++) wmma::fill_fragment(acc[i], 0.f);
#pragma unroll
        for (int tap = 0; tap < 3; tap++) {
#pragma unroll
            for (int ks = 0; ks < 8; ks++) {
                wmma::fragment<wmma::matrix_a, 16, 16, 8, wmma::precision::tf32, wmma::row_major> af;
                wmma::load_matrix_sync(af, sIn + (mt * 16 + tap) * LDS + ks * 8, LDS);
                const float* fb = sW + (size_t)((tap * 8 + ks) * 4) * 128 + lane * 4;
#pragma unroll
                for (int nt = 0; nt < 4; nt++) {
                    wmma::fragment<wmma::matrix_b, 16, 16, 8, wmma::precision::tf32, wmma::row_major> bf;
                    float4 v = *(const float4*)(fb + nt * 128);
                    bf.x[0] = v.x; bf.x[1] = v.y; bf.x[2] = v.z; bf.x[3] = v.w;
                    wmma::mma_sync(acc[nt], af, bf, acc[nt]);
                }
            }
        }
#pragma unroll
        for (int nt = 0; nt < 4; nt++)
            wmma::store_matrix_sync(sOut + mt * 16 * LDS + nt * 16, acc[nt], LDS, wmma::mem_row_major);

        if (doFix) {
            __syncwarp();
            // 2 lanes per row: lane>>1 = row-in-tile, lane&1 = column half
            int r = mt * 16 + (lane >> 1);
            int p = pbase + r;
            bool valid = (p >= 0) && (p < NPTS);
            float* rowp = sOut + r * LDS + (lane & 1) * 32;
            const float* bp = sBiasL + (lane & 1) * 32;
#pragma unroll
            for (int j = 0; j < 8; j++) {
                float4 v = *(float4*)(rowp + j * 4);
                if (valid) {
                    float4 bb = *(const float4*)(bp + j * 4);
                    v.x = fmaxf(v.x + bb.x, 0.f); v.y = fmaxf(v.y + bb.y, 0.f);
                    v.z = fmaxf(v.z + bb.z, 0.f); v.w = fmaxf(v.w + bb.w, 0.f);
                } else {
                    v = make_float4(0.f, 0.f, 0.f, 0.f);
                }
                *(float4*)(rowp + j * 4) = v;
            }
        }
    }
}

// ---------------------------------------------------------------------------
// Fused block kernel: gather(pa) -> conv-bn-relu x2 -> conv-bn -> relu(x+h) -> scatter(pa)
// ---------------------------------------------------------------------------
__global__ __launch_bounds__(NTHREADS, 1)
void block_kernel(const float* __restrict__ xin, float* __restrict__ xout,
                  const void* __restrict__ paPtr,
                  const float* __restrict__ wfrag, const float* __restrict__ bias) {
    extern __shared__ float smem[];
    float* sA    = smem;                       // input (gathered), ROWS x LDS
    float* sB    = sA + ROWS * LDS;            // conv1 out / conv3 out
    float* sC    = sB + ROWS * LDS;            // conv2 out
    float* sW    = sC + ROWS * LDS;            // fragment-order weights: 96 frags x 128
    float* sBias = sW + 96 * 128;              // 3 x 64
    int*   sIdx  = (int*)(sBias + 192);        // gathered source indices

    const int tid   = threadIdx.x;
    const int warp  = tid >> 5;
    const int lane  = tid & 31;
    const int tile0 = blockIdx.x * TILE;
    const int b     = blockIdx.y;
    const int is64  = g_is64;

    // --- permutation indices (row r <-> global gathered pos tile0-3+r) ---
    for (int r = tid; r < TILE + 6; r += NTHREADS) {
        int p = tile0 - 3 + r;
        int v = -1;
        if (p >= 0 && p < NPTS) {
            size_t gp = (size_t)b * NPTS + p;
            v = is64 ? (int)((const long long*)paPtr)[gp] : ((const int*)paPtr)[gp];
        }
        sIdx[r] = v;
    }
    if (tid < 3 * CH) sBias[tid] = bias[tid];
    __syncthreads();

    // --- gather input rows into sA (zero halo) + layer0 fragment weights ---
    for (int it = tid; it < (TILE + 6) * 16; it += NTHREADS) {
        int r = it >> 4, c4 = it & 15;
        int src = sIdx[r];
        float4 v = make_float4(0.f, 0.f, 0.f, 0.f);
        if (src >= 0)
            v = *(const float4*)(xin + ((size_t)b * NPTS + src) * CH + c4 * 4);
        *(float4*)(sA + r * LDS + c4 * 4) = v;
    }
    for (int it = tid; it < 96 * 32; it += NTHREADS)
        *(float4*)(sW + it * 4) = *(const float4*)(wfrag + it * 4);
    __syncthreads();

    // conv1: sA -> sB (rows 0..207; pos = tile0-2+r), fixup bias0+relu inline
    conv_pass(sA, sB, sW, 13, warp, lane, sBias, tile0 - 2, true);
    __syncthreads();

    // stage layer 1 fragment weights
    for (int it = tid; it < 96 * 32; it += NTHREADS)
        *(float4*)(sW + it * 4) = *(const float4*)(wfrag + 96 * 128 + it * 4);
    __syncthreads();

    // conv2: sB -> sC (pos = tile0-1+r), fixup bias1+relu inline
    conv_pass(sB, sC, sW, 13, warp, lane, sBias + 64, tile0 - 1, true);
    __syncthreads();

    // stage layer 2 fragment weights
    for (int it = tid; it < 96 * 32; it += NTHREADS)
        *(float4*)(sW + it * 4) = *(const float4*)(wfrag + 2 * 96 * 128 + it * 4);
    __syncthreads();

    // conv3: sC -> sB (rows 0..191; pos = tile0+r), no fixup (epilogue owns it)
    conv_pass(sC, sB, sW, 12, warp, lane, nullptr, 0, false);
    __syncthreads();

    // epilogue: relu(residual + conv3 + bias2), scatter out[pa[p]] = y[p]
    for (int it = tid; it < TILE * 16; it += NTHREADS) {
        int r = it >> 4, c4 = it & 15;
        int p = tile0 + r;
        if (p >= NPTS) continue;
        int dst = sIdx[r + 3];  // = pa[p]
        float4 h  = *(float4*)(sB + r * LDS + c4 * 4);
        float4 a  = *(float4*)(sA + (r + 3) * LDS + c4 * 4);
        float4 bb = *(float4*)(sBias + 128 + c4 * 4);
        float4 y;
        y.x = fmaxf(a.x + h.x + bb.x, 0.f);
        y.y = fmaxf(a.y + h.y + bb.y, 0.f);
        y.z = fmaxf(a.z + h.z + bb.z, 0.f);
        y.w = fmaxf(a.w + h.w + bb.w, 0.f);
        *(float4*)(xout + ((size_t)b * NPTS + dst) * CH + c4 * 4) = y;
    }
}

// ---------------------------------------------------------------------------
// Launch
// ---------------------------------------------------------------------------
extern "C" void kernel_launch(void* const* d_in, const int* in_sizes, int n_in,
                              void* d_out, int out_size) {
    const float* x      = (const float*)d_in[0];
    const void*  pa1    = d_in[1];
    const void*  pa2    = d_in[3];
    const float* conv_w = (const float*)d_in[5];
    const float* gma    = (const float*)d_in[6];
    const float* bta    = (const float*)d_in[7];
    const float* mean   = (const float*)d_in[8];
    const float* var    = (const float*)d_in[9];

    float* mid;   cudaGetSymbolAddress((void**)&mid,   g_mid);
    float* wfrag; cudaGetSymbolAddress((void**)&wfrag, g_wfrag);
    float* bias;  cudaGetSymbolAddress((void**)&bias,  g_bias);

    const int smemBytes = (3 * ROWS * LDS + 96 * 128 + 192) * 4 + ROWS * 4;
    cudaFuncSetAttribute(block_kernel, cudaFuncAttributeMaxDynamicSharedMemorySize, smemBytes);

    detect_idx_kernel<<<1, 256>>>((const unsigned int*)pa1);
    repack_kernel<<<(NBLK * 3 * CH * CH + 255) / 256, 256>>>(conv_w, gma, bta, mean, var);
    prep_frag_kernel<<<(NBLK * 3 * 3 * 8 * 4 * 32 + 255) / 256, 256>>>();

    dim3 grid((NPTS + TILE - 1) / TILE, NBATCH);
    // block 0: x -> g_mid (perm1, fragment slab 0)
    block_kernel<<<grid, NTHREADS, smemBytes>>>(x, mid, pa1, wfrag, bias);
    // block 1: g_mid -> d_out (perm2, fragment slab 1)
    block_kernel<<<grid, NTHREADS, smemBytes>>>(mid, (float*)d_out, pa2,
                                                wfrag + 3 * 96 * 128, bias + 3 * CH);
}

// round 5
// speedup vs baseline: 2.2995x; 1.2989x over previous
#include <cuda_runtime.h>
#include <mma.h>
#include <cstdint>
#include <cstddef>

// tcgen05 is an arch-SPECIFIC feature: present only when compiling for sm_103a
// (or other *a targets). The harness also runs a plain compute_103 pass, which
// must get a tcgen05-free body.
#if defined(__CUDA_ARCH__) && (defined(__CUDA_ARCH_FEAT_SM103_ALL) || defined(__CUDA_ARCH_FEAT_SM100_ALL) || defined(__CUDA_ARCH_FEAT_SM101_ALL))
#define HAS_TC 1
#else
#define HAS_TC 0
#endif

// Problem constants
#define NBATCH   2
#define CH       64
#define NPTS     262144
#define NBLK     2

// Tiling
#define TILE     224
#define R_IN     230          // input rows  (pos tile0-3 .. tile0+226)
#define R_B1     228          // conv1 rows  (pos tile0-2 .. tile0+225)
#define R_B2     226          // conv2 rows  (pos tile0-1 .. tile0+224)
#define NTHREADS 256
#define GRID_X   ((NPTS + TILE - 1) / TILE)   // 1171

// SMEM byte offsets (canonical no-swizzle K-major chunks: addr = c*ROWS*16 + r*16)
#define OFF_IN   0
#define OFF_B1   (R_IN * 256)                    // 58880
#define OFF_B2   (OFF_B1 + R_B1 * 256)           // 117248
#define OFF_W    (OFF_B2 + R_B2 * 256)           // 175104 (48 KB: [tap][i16][o row 16B])
#define OFF_BIAS (OFF_W + 49152)                 // 224256 (3 x 64 floats)
#define OFF_IDX  (OFF_BIAS + 768)                // 225024 (230 ints)
#define OFF_TM   (OFF_IDX + 960)                 // 225984 (tmem ptr, 16B)
#define OFF_MBAR (OFF_TM + 16)                   // 226000
#define SMEM_BYTES (OFF_MBAR + 16)               // 226016

// idesc: D=f32, A=B=tf32, N=64 (8<<17), M=128 (8<<24), K-major, cg1
#define IDESC 0x08100910u

// Device scratch
__device__ float g_mid[(size_t)NBATCH * NPTS * CH];
__device__ float g_wt2[NBLK * 3 * 3 * 16 * 256];   // [bl(6)][tap][i16][o*4+i%4], BN-folded tf32
__device__ float g_bias[NBLK * 3 * CH];
__device__ int   g_is64;

// ---------------------------------------------------------------------------
// Common helpers
// ---------------------------------------------------------------------------
__device__ __forceinline__ uint32_t smem_u32(const void* p) {
    uint32_t a;
    asm("{ .reg .u64 t; cvta.to.shared.u64 t, %1; cvt.u32.u64 %0, t; }" : "=r"(a) : "l"(p));
    return a;
}

#if HAS_TC
// ---------------------------------------------------------------------------
// tcgen05 helpers (sm_103a-only compilation path)
// ---------------------------------------------------------------------------
__device__ __forceinline__ uint32_t elect_one() {
    uint32_t p;
    asm volatile("{\n\t.reg .pred p;\n\telect.sync _|p, 0xFFFFFFFF;\n\tselp.b32 %0, 1, 0, p;\n\t}" : "=r"(p));
    return p;
}
#define TCGEN05_ALLOC(sl, n)  asm volatile("tcgen05.alloc.cta_group::1.sync.aligned.shared::cta.b32 [%0], %1;" :: "r"(sl), "r"((uint32_t)(n)) : "memory")
#define TCGEN05_DEALLOC(t, n) asm volatile("tcgen05.dealloc.cta_group::1.sync.aligned.b32 %0, %1;" :: "r"(t), "r"((uint32_t)(n)))
#define TCGEN05_RELINQ()      asm volatile("tcgen05.relinquish_alloc_permit.cta_group::1.sync.aligned;")
#define TCGEN05_COMMIT(mb)    asm volatile("tcgen05.commit.cta_group::1.mbarrier::arrive::one.shared::cluster.b64 [%0];" :: "r"(mb) : "memory")
#define TCGEN05_WAIT_LD()     asm volatile("tcgen05.wait::ld.sync.aligned;" ::: "memory")
#define TCGEN05_FENCE_AFTER() asm volatile("tcgen05.fence::after_thread_sync;" ::: "memory")
#define TCGEN05_FENCE_BEFORE() asm volatile("tcgen05.fence::before_thread_sync;" ::: "memory")
#define FENCE_ASYNC()         asm volatile("fence.proxy.async.shared::cta;" ::: "memory")
#define MBAR_INIT(mb, n)      asm volatile("mbarrier.init.shared.b64 [%0], %1;" :: "r"(mb), "r"((uint32_t)(n)) : "memory")

#define MBAR_WAIT(mb, ph) do {                                                   \
    uint32_t _m = (mb), _p = (ph), _d;                                           \
    asm volatile("{\n\t.reg .pred p;\n\t"                                        \
        "mbarrier.try_wait.parity.acquire.cta.shared::cta.b64 p, [%1], %2;\n\t"  \
        "selp.b32 %0, 1, 0, p;\n\t}" : "=r"(_d) : "r"(_m), "r"(_p) : "memory");  \
    if (!_d) {                                                                   \
        asm volatile("{\n\t.reg .pred P1;\n\t"                                   \
        "WL_%=:\n\t"                                                             \
        "mbarrier.try_wait.parity.acquire.cta.shared::cta.b64 P1, [%0], %1, 0x989680;\n\t" \
        "@P1 bra.uni WD_%=;\n\t"                                                 \
        "bra.uni WL_%=;\n\t"                                                     \
        "WD_%=:\n\t}" :: "r"(_m), "r"(_p) : "memory");                           \
    }                                                                            \
} while (0)

#define LDTM_X32(r, addr) \
    asm volatile("tcgen05.ld.sync.aligned.32x32b.x32.b32 " \
        "{%0, %1, %2, %3, %4, %5, %6, %7, " \
        " %8, %9, %10, %11, %12, %13, %14, %15, " \
        " %16, %17, %18, %19, %20, %21, %22, %23, " \
        " %24, %25, %26, %27, %28, %29, %30, %31}, [%32];" \
        : "=r"((r)[0]),  "=r"((r)[1]),  "=r"((r)[2]),  "=r"((r)[3]), \
          "=r"((r)[4]),  "=r"((r)[5]),  "=r"((r)[6]),  "=r"((r)[7]), \
          "=r"((r)[8]),  "=r"((r)[9]),  "=r"((r)[10]), "=r"((r)[11]), \
          "=r"((r)[12]), "=r"((r)[13]), "=r"((r)[14]), "=r"((r)[15]), \
          "=r"((r)[16]), "=r"((r)[17]), "=r"((r)[18]), "=r"((r)[19]), \
          "=r"((r)[20]), "=r"((r)[21]), "=r"((r)[22]), "=r"((r)[23]), \
          "=r"((r)[24]), "=r"((r)[25]), "=r"((r)[26]), "=r"((r)[27]), \
          "=r"((r)[28]), "=r"((r)[29]), "=r"((r)[30]), "=r"((r)[31]) \
        : "r"(addr))

__device__ __forceinline__ void mma_tf32(uint32_t d, uint64_t ad, uint64_t bd, uint32_t en) {
    asm volatile("{\n\t.reg .pred p;\n\tsetp.ne.u32 p, %4, 0;\n\t"
        "tcgen05.mma.cta_group::1.kind::tf32 [%0], %1, %2, %3, {%5, %5, %5, %5}, p;\n\t}"
        :: "r"(d), "l"(ad), "l"(bd), "r"(IDESC), "r"(en), "r"(0u) : "memory");
}

// No-swizzle SMEM descriptor (layout_type=0): LBO/SBO in 16B units
__device__ __forceinline__ uint64_t make_desc(uint32_t addr, uint32_t lbo, uint32_t sbo) {
    uint64_t d = (uint64_t)((addr >> 4) & 0x3FFF);
    d |= (uint64_t)(lbo & 0x3FFF) << 16;
    d |= (uint64_t)(sbo & 0x3FFF) << 32;
    d |= (uint64_t)1 << 46;     // version = 1 (Blackwell)
    return d;
}

// One conv layer: 2 M-tiles x 3 taps x 8 k-steps, then commit.
__device__ __forceinline__ void issue_conv(uint32_t aAddr, int aLBO, uint32_t wAddr,
                                           uint32_t tmem, uint32_t mbar) {
    uint64_t ab = make_desc(aAddr, aLBO, 8);
    uint64_t bb = make_desc(wAddr, 64, 8);
#pragma unroll
    for (int T = 0; T < 2; T++) {
        uint32_t en = 0;
#pragma unroll
        for (int tap = 0; tap < 3; tap++)
#pragma unroll
            for (int ks = 0; ks < 8; ks++) {
                mma_tf32(tmem + T * 64,
                         ab + (uint64_t)(T * 128 + tap + 2 * ks * aLBO),
                         bb + (uint64_t)(tap * 1024 + 2 * ks * 64), en);
                en = 1;
            }
    }
    TCGEN05_COMMIT(mbar);
}

// Intermediate epilogue: thread tid owns output row tid of this pass.
__device__ __forceinline__ void epi_mid(char* smem, int offOut, int rowsOut, int live,
                                        int posBase, const float* sBiasL,
                                        uint32_t dcol, int tid) {
    int r = tid;
    bool store = (r < live);
    bool zero = (posBase + r < 0) || (posBase + r >= NPTS);
#pragma unroll
    for (int half = 0; half < 2; half++) {
        uint32_t rg[32];
        LDTM_X32(rg, dcol + half * 32);
        TCGEN05_WAIT_LD();
        if (store) {
#pragma unroll
            for (int j = 0; j < 8; j++) {
                int c = half * 8 + j;
                float4 v = make_float4(0.f, 0.f, 0.f, 0.f);
                if (!zero) {
                    float4 bb = *(const float4*)(sBiasL + c * 4);
                    v.x = fmaxf(__uint_as_float(rg[j * 4 + 0]) + bb.x, 0.f);
                    v.y = fmaxf(__uint_as_float(rg[j * 4 + 1]) + bb.y, 0.f);
                    v.z = fmaxf(__uint_as_float(rg[j * 4 + 2]) + bb.z, 0.f);
                    v.w = fmaxf(__uint_as_float(rg[j * 4 + 3]) + bb.w, 0.f);
                }
                *(float4*)(smem + offOut + ((size_t)c * rowsOut + r) * 16) = v;
            }
        }
    }
}
#else  // !HAS_TC -----------------------------------------------------------
// Scalar fallback conv for the non-'a' compilation pass (correct, slow; only
// ever runs if the driver JITs the compute_103 PTX instead of loading the
// sm_103a cubin). Same smem layout and weight format as the tcgen05 path.
__device__ void conv_scalar(char* smem, int offIn, int rowsIn, int offOut, int rowsOut,
                            int live, int posBase, const float* sW,
                            const float* sBiasL, int tid) {
    for (int r = tid; r < live; r += NTHREADS) {
        float acc[CH];
#pragma unroll
        for (int o = 0; o < CH; o++) acc[o] = 0.f;
        bool zero = (posBase + r < 0) || (posBase + r >= NPTS);
        if (!zero) {
            for (int tap = 0; tap < 3; tap++)
                for (int ci = 0; ci < 16; ci++) {
                    const float* inp = (const float*)(smem + offIn + ((size_t)ci * rowsIn + r + tap) * 16);
                    float x0 = inp[0], x1 = inp[1], x2 = inp[2], x3 = inp[3];
                    const float* wp = sW + tap * 4096 + ci * 256;
                    for (int o = 0; o < CH; o++)
                        acc[o] += x0 * wp[o * 4] + x1 * wp[o * 4 + 1]
                                + x2 * wp[o * 4 + 2] + x3 * wp[o * 4 + 3];
                }
        }
        for (int ci = 0; ci < 16; ci++) {
            float4 v = make_float4(0.f, 0.f, 0.f, 0.f);
            if (!zero) {
                if (sBiasL) {
                    v.x = fmaxf(acc[ci * 4 + 0] + sBiasL[ci * 4 + 0], 0.f);
                    v.y = fmaxf(acc[ci * 4 + 1] + sBiasL[ci * 4 + 1], 0.f);
                    v.z = fmaxf(acc[ci * 4 + 2] + sBiasL[ci * 4 + 2], 0.f);
                    v.w = fmaxf(acc[ci * 4 + 3] + sBiasL[ci * 4 + 3], 0.f);
                } else {
                    v = make_float4(acc[ci * 4], acc[ci * 4 + 1], acc[ci * 4 + 2], acc[ci * 4 + 3]);
                }
            }
            *(float4*)(smem + offOut + ((size_t)ci * rowsOut + r) * 16) = v;
        }
    }
}
#endif // HAS_TC

// ---------------------------------------------------------------------------
// Prep kernels
// ---------------------------------------------------------------------------
__global__ void detect_idx_kernel(const unsigned int* __restrict__ w) {
    __shared__ int any;
    if (threadIdx.x == 0) any = 0;
    __syncthreads();
    int local = 0;
    for (int i = threadIdx.x; i < 2048; i += blockDim.x)
        if (w[2 * i + 1] != 0u) local = 1;
    if (local) atomicOr(&any, 1);
    __syncthreads();
    if (threadIdx.x == 0) g_is64 = any ? 0 : 1;
}

// Repack: fold BN into W, canonical B layout per (bl, tap): [i16][o rows of 16B]
__global__ void repack_kernel(const float* __restrict__ w,
                              const float* __restrict__ gm,
                              const float* __restrict__ bt,
                              const float* __restrict__ mn,
                              const float* __restrict__ vr) {
    int idx = blockIdx.x * blockDim.x + threadIdx.x;
    if (idx >= NBLK * 3 * CH * CH) return;
    int i  = idx & 63;
    int o  = (idx >> 6) & 63;
    int bl = idx >> 12;
    float scale = gm[bl * CH + o] * rsqrtf(vr[bl * CH + o] + 1e-5f);
#pragma unroll
    for (int t = 0; t < 3; t++) {
        float val = w[(((size_t)bl * CH + o) * CH + i) * 3 + t] * scale;
        g_wt2[(size_t)bl * 12288 + ((t * 16 + (i >> 2)) * 256) + o * 4 + (i & 3)] =
            nvcuda::wmma::__float_to_tf32(val);
    }
    if (i == 0)
        g_bias[bl * CH + o] = bt[bl * CH + o] - mn[bl * CH + o] * scale;
}

// ---------------------------------------------------------------------------
// Fused block kernel: gather -> conv x3 -> residual -> scatter
// ---------------------------------------------------------------------------
__global__ __launch_bounds__(NTHREADS, 1)
void block_kernel(const float* __restrict__ xin, float* __restrict__ xout,
                  const void* __restrict__ paPtr,
                  const float* __restrict__ wslab, const float* __restrict__ bias) {
    extern __shared__ char smem[];
    const int tid  = threadIdx.x;
    const int warp = tid >> 5;
    const int tile0 = blockIdx.x * TILE;
    const int b     = blockIdx.y;
    const int is64  = g_is64;

    const uint32_t sbase = smem_u32(smem);
    int*   sIdx  = (int*)(smem + OFF_IDX);
    float* sBias = (float*)(smem + OFF_BIAS);
    float* sW    = (float*)(smem + OFF_W);

#if HAS_TC
    const uint32_t mbar = sbase + OFF_MBAR;
    if (tid == 0) MBAR_INIT(mbar, 1);
    if (warp == 0) {
        TCGEN05_ALLOC(sbase + OFF_TM, 128);
        TCGEN05_RELINQ();
    }
#endif

    // permutation indices: row r <-> pos tile0-3+r
    for (int r = tid; r < R_IN; r += NTHREADS) {
        int p = tile0 - 3 + r;
        int v = -1;
        if (p >= 0 && p < NPTS) {
            size_t gp = (size_t)b * NPTS + p;
            v = is64 ? (int)((const long long*)paPtr)[gp] : ((const int*)paPtr)[gp];
        }
        sIdx[r] = v;
    }
    if (tid < 3 * CH) sBias[tid] = bias[tid];
    __syncthreads();

    // gather input into canonical layout + stage layer-0 weights
    for (int it = tid; it < R_IN * 16; it += NTHREADS) {
        int r = it >> 4, c = it & 15;
        int src = sIdx[r];
        float4 v = make_float4(0.f, 0.f, 0.f, 0.f);
        if (src >= 0)
            v = *(const float4*)(xin + ((size_t)b * NPTS + src) * CH + c * 4);
        *(float4*)(smem + OFF_IN + ((size_t)c * R_IN + r) * 16) = v;
    }
    for (int it = tid; it < 3072; it += NTHREADS)
        ((float4*)sW)[it] = ((const float4*)wslab)[it];

#if HAS_TC
    uint32_t tmem;
    asm volatile("ld.shared.b32 %0, [%1];" : "=r"(tmem) : "r"(sbase + OFF_TM));
    FENCE_ASYNC();
    __syncthreads();

    const uint32_t dcol = tmem + ((warp >= 4) ? 64 : 0);

    // ---- conv1: IN -> TMEM -> B1 ----
    if (warp == 0 && elect_one())
        issue_conv(sbase + OFF_IN, R_IN, sbase + OFF_W, tmem, mbar);
    MBAR_WAIT(mbar, 0);
    TCGEN05_FENCE_AFTER();
    {   // prefetch layer-1 weights while epiloguing
        float4 wreg[12];
#pragma unroll
        for (int k = 0; k < 12; k++) wreg[k] = ((const float4*)(wslab + 12288))[tid + k * 256];
        epi_mid(smem, OFF_B1, R_B1, R_B1, tile0 - 2, sBias, dcol, tid);
#pragma unroll
        for (int k = 0; k < 12; k++) ((float4*)sW)[tid + k * 256] = wreg[k];
    }
    TCGEN05_FENCE_BEFORE();
    FENCE_ASYNC();
    __syncthreads();

    // ---- conv2: B1 -> TMEM -> B2 ----
    if (warp == 0 && elect_one())
        issue_conv(sbase + OFF_B1, R_B1, sbase + OFF_W, tmem, mbar);
    MBAR_WAIT(mbar, 1);
    TCGEN05_FENCE_AFTER();
    {
        float4 wreg[12];
#pragma unroll
        for (int k = 0; k < 12; k++) wreg[k] = ((const float4*)(wslab + 24576))[tid + k * 256];
        epi_mid(smem, OFF_B2, R_B2, R_B2, tile0 - 1, sBias + 64, dcol, tid);
#pragma unroll
        for (int k = 0; k < 12; k++) ((float4*)sW)[tid + k * 256] = wreg[k];
    }
    TCGEN05_FENCE_BEFORE();
    FENCE_ASYNC();
    __syncthreads();

    // ---- conv3: B2 -> TMEM ----
    if (warp == 0 && elect_one())
        issue_conv(sbase + OFF_B2, R_B2, sbase + OFF_W, tmem, mbar);
    MBAR_WAIT(mbar, 0);
    TCGEN05_FENCE_AFTER();

    // ---- final epilogue: y = relu(residual + h3 + bias2), scatter ----
    {
        int r = tid;
        bool go = (r < TILE) && (tile0 + r < NPTS);
        int dst = go ? sIdx[r + 3] : 0;
        float* outp = xout + ((size_t)b * NPTS + dst) * CH;
#pragma unroll
        for (int half = 0; half < 2; half++) {
            uint32_t rg[32];
            LDTM_X32(rg, dcol + half * 32);
            TCGEN05_WAIT_LD();
            if (go) {
#pragma unroll
                for (int j = 0; j < 8; j++) {
                    int c = half * 8 + j;
                    float4 res = *(const float4*)(smem + OFF_IN + ((size_t)c * R_IN + (r + 3)) * 16);
                    float4 bb  = *(const float4*)(sBias + 128 + c * 4);
                    float4 y;
                    y.x = fmaxf(res.x + __uint_as_float(rg[j * 4 + 0]) + bb.x, 0.f);
                    y.y = fmaxf(res.y + __uint_as_float(rg[j * 4 + 1]) + bb.y, 0.f);
                    y.z = fmaxf(res.z + __uint_as_float(rg[j * 4 + 2]) + bb.z, 0.f);
                    y.w = fmaxf(res.w + __uint_as_float(rg[j * 4 + 3]) + bb.w, 0.f);
                    *(float4*)(outp + c * 4) = y;
                }
            }
        }
    }
    TCGEN05_FENCE_BEFORE();
    __syncthreads();
    if (warp == 0) TCGEN05_DEALLOC(tmem, 128);

#else // ---- scalar fallback path (compute_103 JIT image only) ----
    __syncthreads();
    conv_scalar(smem, OFF_IN, R_IN, OFF_B1, R_B1, R_B1, tile0 - 2, sW, sBias, tid);
    __syncthreads();
    for (int it = tid; it < 3072; it += NTHREADS)
        ((float4*)sW)[it] = ((const float4*)(wslab + 12288))[it];
    __syncthreads();
    conv_scalar(smem, OFF_B1, R_B1, OFF_B2, R_B2, R_B2, tile0 - 1, sW, sBias + 64, tid);
    __syncthreads();
    for (int it = tid; it < 3072; it += NTHREADS)
        ((float4*)sW)[it] = ((const float4*)(wslab + 24576))[it];
    __syncthreads();
    // conv3 raw (no bias/relu) back into B1
    conv_scalar(smem, OFF_B2, R_B2, OFF_B1, R_B1, TILE, tile0, sW, nullptr, tid);
    __syncthreads();
    for (int it = tid; it < TILE * 16; it += NTHREADS) {
        int r = it >> 4, c = it & 15;
        if (tile0 + r >= NPTS) continue;
        int dst = sIdx[r + 3];
        float4 h   = *(const float4*)(smem + OFF_B1 + ((size_t)c * R_B1 + r) * 16);
        float4 res = *(const float4*)(smem + OFF_IN + ((size_t)c * R_IN + (r + 3)) * 16);
        float4 bb  = *(const float4*)(sBias + 128 + c * 4);
        float4 y;
        y.x = fmaxf(res.x + h.x + bb.x, 0.f);
        y.y = fmaxf(res.y + h.y + bb.y, 0.f);
        y.z = fmaxf(res.z + h.z + bb.z, 0.f);
        y.w = fmaxf(res.w + h.w + bb.w, 0.f);
        *(float4*)(xout + ((size_t)b * NPTS + dst) * CH + c * 4) = y;
    }
#endif
}

// ---------------------------------------------------------------------------
// Launch
// ---------------------------------------------------------------------------
extern "C" void kernel_launch(void* const* d_in, const int* in_sizes, int n_in,
                              void* d_out, int out_size) {
    const float* x      = (const float*)d_in[0];
    const void*  pa1    = d_in[1];
    const void*  pa2    = d_in[3];
    const float* conv_w = (const float*)d_in[5];
    const float* gma    = (const float*)d_in[6];
    const float* bta    = (const float*)d_in[7];
    const float* mean   = (const float*)d_in[8];
    const float* var    = (const float*)d_in[9];

    float* mid;  cudaGetSymbolAddress((void**)&mid,  g_mid);
    float* wt2;  cudaGetSymbolAddress((void**)&wt2,  g_wt2);
    float* bias; cudaGetSymbolAddress((void**)&bias, g_bias);

    cudaFuncSetAttribute(block_kernel, cudaFuncAttributeMaxDynamicSharedMemorySize, SMEM_BYTES);

    detect_idx_kernel<<<1, 256>>>((const unsigned int*)pa1);
    repack_kernel<<<(NBLK * 3 * CH * CH + 255) / 256, 256>>>(conv_w, gma, bta, mean, var);

    dim3 grid(GRID_X, NBATCH);
    block_kernel<<<grid, NTHREADS, SMEM_BYTES>>>(x, mid, pa1, wt2, bias);
    block_kernel<<<grid, NTHREADS, SMEM_BYTES>>>(mid, (float*)d_out, pa2,
                                                 wt2 + 3 * 12288, bias + 3 * CH);
}

// round 6
// speedup vs baseline: 4.5434x; 1.9758x over previous
#include <cuda_runtime.h>
#include <mma.h>
#include <cstdint>
#include <cstddef>

// tcgen05 is arch-SPECIFIC: only on the sm_103a pass; plain compute_103 gets a fallback.
#if defined(__CUDA_ARCH__) && (defined(__CUDA_ARCH_FEAT_SM103_ALL) || defined(__CUDA_ARCH_FEAT_SM100_ALL) || defined(__CUDA_ARCH_FEAT_SM101_ALL))
#define HAS_TC 1
#else
#define HAS_TC 0
#endif

// Problem constants
#define NBATCH   2
#define CH       64
#define NPTS     262144
#define NBLK     2

// Tiling
#define TILE     224
#define R_IN     230
#define R_B1     228
#define R_B2     226
#define NTHREADS 512
#define GRID_X   ((NPTS + TILE - 1) / TILE)   // 1171

// SMEM byte offsets (canonical K-major chunks: addr = c*ROWS*16 + r*16)
#define OFF_IN   0
#define OFF_B1   (R_IN * 256)
#define OFF_B2   (OFF_B1 + R_B1 * 256)
#define OFF_W    (OFF_B2 + R_B2 * 256)           // 48 KB slab: [tap][i16][o row 16B]
#define OFF_BIAS (OFF_W + 49152)
#define OFF_IDX  (OFF_BIAS + 768)
#define OFF_TM   (OFF_IDX + 960)
#define OFF_MBAR (OFF_TM + 16)                   // two mbarriers (8B each)
#define SMEM_BYTES (OFF_MBAR + 16)

// idesc: D=f32, A=B=tf32, N=64, M=128, K-major, cg1
#define IDESC 0x08100910u

// Device scratch
__device__ float g_mid[(size_t)NBATCH * NPTS * CH];
__device__ float g_wt2[NBLK * 3 * 3 * 16 * 256];   // [bl(6)][tap][i16][o*4+i%4], BN-folded tf32
__device__ float g_bias[NBLK * 3 * CH];
__device__ int   g_is64;

__device__ __forceinline__ uint32_t smem_u32(const void* p) {
    uint32_t a;
    asm("{ .reg .u64 t; cvta.to.shared.u64 t, %1; cvt.u32.u64 %0, t; }" : "=r"(a) : "l"(p));
    return a;
}

#if HAS_TC
// ---------------------------------------------------------------------------
__device__ __forceinline__ uint32_t elect_one() {
    uint32_t p;
    asm volatile("{\n\t.reg .pred p;\n\telect.sync _|p, 0xFFFFFFFF;\n\tselp.b32 %0, 1, 0, p;\n\t}" : "=r"(p));
    return p;
}
#define TCGEN05_ALLOC(sl, n)  asm volatile("tcgen05.alloc.cta_group::1.sync.aligned.shared::cta.b32 [%0], %1;" :: "r"(sl), "r"((uint32_t)(n)) : "memory")
#define TCGEN05_DEALLOC(t, n) asm volatile("tcgen05.dealloc.cta_group::1.sync.aligned.b32 %0, %1;" :: "r"(t), "r"((uint32_t)(n)))
#define TCGEN05_RELINQ()      asm volatile("tcgen05.relinquish_alloc_permit.cta_group::1.sync.aligned;")
#define TCGEN05_COMMIT(mb)    asm volatile("tcgen05.commit.cta_group::1.mbarrier::arrive::one.shared::cluster.b64 [%0];" :: "r"(mb) : "memory")
#define TCGEN05_WAIT_LD()     asm volatile("tcgen05.wait::ld.sync.aligned;" ::: "memory")
#define TCGEN05_FENCE_AFTER() asm volatile("tcgen05.fence::after_thread_sync;" ::: "memory")
#define TCGEN05_FENCE_BEFORE() asm volatile("tcgen05.fence::before_thread_sync;" ::: "memory")
#define FENCE_ASYNC()         asm volatile("fence.proxy.async.shared::cta;" ::: "memory")
#define MBAR_INIT(mb, n)      asm volatile("mbarrier.init.shared.b64 [%0], %1;" :: "r"(mb), "r"((uint32_t)(n)) : "memory")

#define MBAR_WAIT(mb, ph) do {                                                   \
    uint32_t _m = (mb), _p = (ph), _d;                                           \
    asm volatile("{\n\t.reg .pred p;\n\t"                                        \
        "mbarrier.try_wait.parity.acquire.cta.shared::cta.b64 p, [%1], %2;\n\t"  \
        "selp.b32 %0, 1, 0, p;\n\t}" : "=r"(_d) : "r"(_m), "r"(_p) : "memory");  \
    if (!_d) {                                                                   \
        asm volatile("{\n\t.reg .pred P1;\n\t"                                   \
        "WL_%=:\n\t"                                                             \
        "mbarrier.try_wait.parity.acquire.cta.shared::cta.b64 P1, [%0], %1, 0x989680;\n\t" \
        "@P1 bra.uni WD_%=;\n\t"                                                 \
        "bra.uni WL_%=;\n\t"                                                     \
        "WD_%=:\n\t}" :: "r"(_m), "r"(_p) : "memory");                           \
    }                                                                            \
} while (0)

#define LDTM_X32(r, addr) \
    asm volatile("tcgen05.ld.sync.aligned.32x32b.x32.b32 " \
        "{%0, %1, %2, %3, %4, %5, %6, %7, " \
        " %8, %9, %10, %11, %12, %13, %14, %15, " \
        " %16, %17, %18, %19, %20, %21, %22, %23, " \
        " %24, %25, %26, %27, %28, %29, %30, %31}, [%32];" \
        : "=r"((r)[0]),  "=r"((r)[1]),  "=r"((r)[2]),  "=r"((r)[3]), \
          "=r"((r)[4]),  "=r"((r)[5]),  "=r"((r)[6]),  "=r"((r)[7]), \
          "=r"((r)[8]),  "=r"((r)[9]),  "=r"((r)[10]), "=r"((r)[11]), \
          "=r"((r)[12]), "=r"((r)[13]), "=r"((r)[14]), "=r"((r)[15]), \
          "=r"((r)[16]), "=r"((r)[17]), "=r"((r)[18]), "=r"((r)[19]), \
          "=r"((r)[20]), "=r"((r)[21]), "=r"((r)[22]), "=r"((r)[23]), \
          "=r"((r)[24]), "=r"((r)[25]), "=r"((r)[26]), "=r"((r)[27]), \
          "=r"((r)[28]), "=r"((r)[29]), "=r"((r)[30]), "=r"((r)[31]) \
        : "r"(addr))

__device__ __forceinline__ void mma_tf32(uint32_t d, uint64_t ad, uint64_t bd, uint32_t en) {
    asm volatile("{\n\t.reg .pred p;\n\tsetp.ne.u32 p, %4, 0;\n\t"
        "tcgen05.mma.cta_group::1.kind::tf32 [%0], %1, %2, %3, {%5, %5, %5, %5}, p;\n\t}"
        :: "r"(d), "l"(ad), "l"(bd), "r"(IDESC), "r"(en), "r"(0u) : "memory");
}

__device__ __forceinline__ uint64_t make_desc(uint32_t addr, uint32_t lbo, uint32_t sbo) {
    uint64_t d = (uint64_t)((addr >> 4) & 0x3FFF);
    d |= (uint64_t)(lbo & 0x3FFF) << 16;
    d |= (uint64_t)(sbo & 0x3FFF) << 32;
    d |= (uint64_t)1 << 46;
    return d;
}

// One conv layer, per-M-tile commit: tile0 -> mbar0, tile1 -> mbar1.
__device__ __forceinline__ void issue_conv(uint32_t aAddr, int aLBO, uint32_t wAddr,
                                           uint32_t tmem, uint32_t mbar) {
    uint64_t ab = make_desc(aAddr, aLBO, 8);
    uint64_t bb = make_desc(wAddr, 64, 8);
#pragma unroll
    for (int T = 0; T < 2; T++) {
        uint32_t en = 0;
#pragma unroll
        for (int tap = 0; tap < 3; tap++)
#pragma unroll
            for (int ks = 0; ks < 8; ks++) {
                mma_tf32(tmem + T * 64,
                         ab + (uint64_t)(T * 128 + tap + 2 * ks * aLBO),
                         bb + (uint64_t)(tap * 1024 + 2 * ks * 64), en);
                en = 1;
            }
        TCGEN05_COMMIT(mbar + T * 8);
    }
}
#else  // !HAS_TC -----------------------------------------------------------
// Scalar fallback (only runs if the driver JITs the compute_103 PTX).
__device__ void conv_scalar(char* smem, int offIn, int rowsIn, int offOut, int rowsOut,
                            int live, int posBase, const float* sW,
                            const float* sBiasL, int tid) {
    for (int r = tid; r < live; r += NTHREADS) {
        float acc[CH];
#pragma unroll
        for (int o = 0; o < CH; o++) acc[o] = 0.f;
        bool zero = (posBase + r < 0) || (posBase + r >= NPTS);
        if (!zero) {
            for (int tap = 0; tap < 3; tap++)
                for (int ci = 0; ci < 16; ci++) {
                    const float* inp = (const float*)(smem + offIn + ((size_t)ci * rowsIn + r + tap) * 16);
                    float x0 = inp[0], x1 = inp[1], x2 = inp[2], x3 = inp[3];
                    const float* wp = sW + tap * 4096 + ci * 256;
                    for (int o = 0; o < CH; o++)
                        acc[o] += x0 * wp[o * 4] + x1 * wp[o * 4 + 1]
                                + x2 * wp[o * 4 + 2] + x3 * wp[o * 4 + 3];
                }
        }
        for (int ci = 0; ci < 16; ci++) {
            float4 v = make_float4(0.f, 0.f, 0.f, 0.f);
            if (!zero) {
                if (sBiasL) {
                    v.x = fmaxf(acc[ci * 4 + 0] + sBiasL[ci * 4 + 0], 0.f);
                    v.y = fmaxf(acc[ci * 4 + 1] + sBiasL[ci * 4 + 1], 0.f);
                    v.z = fmaxf(acc[ci * 4 + 2] + sBiasL[ci * 4 + 2], 0.f);
                    v.w = fmaxf(acc[ci * 4 + 3] + sBiasL[ci * 4 + 3], 0.f);
                } else {
                    v = make_float4(acc[ci * 4], acc[ci * 4 + 1], acc[ci * 4 + 2], acc[ci * 4 + 3]);
                }
            }
            *(float4*)(smem + offOut + ((size_t)ci * rowsOut + r) * 16) = v;
        }
    }
}
#endif // HAS_TC

// ---------------------------------------------------------------------------
// Prep kernels
// ---------------------------------------------------------------------------
__global__ void detect_idx_kernel(const unsigned int* __restrict__ w) {
    __shared__ int any;
    if (threadIdx.x == 0) any = 0;
    __syncthreads();
    int local = 0;
    for (int i = threadIdx.x; i < 2048; i += blockDim.x)
        if (w[2 * i + 1] != 0u) local = 1;
    if (local) atomicOr(&any, 1);
    __syncthreads();
    if (threadIdx.x == 0) g_is64 = any ? 0 : 1;
}

__global__ void repack_kernel(const float* __restrict__ w,
                              const float* __restrict__ gm,
                              const float* __restrict__ bt,
                              const float* __restrict__ mn,
                              const float* __restrict__ vr) {
    int idx = blockIdx.x * blockDim.x + threadIdx.x;
    if (idx >= NBLK * 3 * CH * CH) return;
    int i  = idx & 63;
    int o  = (idx >> 6) & 63;
    int bl = idx >> 12;
    float scale = gm[bl * CH + o] * rsqrtf(vr[bl * CH + o] + 1e-5f);
#pragma unroll
    for (int t = 0; t < 3; t++) {
        float val = w[(((size_t)bl * CH + o) * CH + i) * 3 + t] * scale;
        g_wt2[(size_t)bl * 12288 + ((t * 16 + (i >> 2)) * 256) + o * 4 + (i & 3)] =
            nvcuda::wmma::__float_to_tf32(val);
    }
    if (i == 0)
        g_bias[bl * CH + o] = bt[bl * CH + o] - mn[bl * CH + o] * scale;
}

// ---------------------------------------------------------------------------
// Fused block kernel: gather -> conv x3 -> residual -> scatter
// ---------------------------------------------------------------------------
__global__ __launch_bounds__(NTHREADS, 1)
void block_kernel(const float* __restrict__ xin, float* __restrict__ xout,
                  const void* __restrict__ paPtr,
                  const float* __restrict__ wslab, const float* __restrict__ bias) {
    extern __shared__ char smem[];
    const int tid  = threadIdx.x;
    const int warp = tid >> 5;
    const int lane = tid & 31;
    const int tile0 = blockIdx.x * TILE;
    const int b     = blockIdx.y;
    const int is64  = g_is64;

    const uint32_t sbase = smem_u32(smem);
    int*   sIdx  = (int*)(smem + OFF_IDX);
    float* sBias = (float*)(smem + OFF_BIAS);
    float* sW    = (float*)(smem + OFF_W);

#if HAS_TC
    const uint32_t mbar = sbase + OFF_MBAR;
    if (tid == 0) { MBAR_INIT(mbar, 1); MBAR_INIT(mbar + 8, 1); }
    if (warp == 0) {
        TCGEN05_ALLOC(sbase + OFF_TM, 128);
        TCGEN05_RELINQ();
    }
#endif

    // permutation indices: row r <-> pos tile0-3+r
    for (int r = tid; r < R_IN; r += NTHREADS) {
        int p = tile0 - 3 + r;
        int v = -1;
        if (p >= 0 && p < NPTS) {
            size_t gp = (size_t)b * NPTS + p;
            v = is64 ? (int)((const long long*)paPtr)[gp] : ((const int*)paPtr)[gp];
        }
        sIdx[r] = v;
    }
    if (tid < 3 * CH) sBias[tid] = bias[tid];
    __syncthreads();

    // gather input into canonical layout + stage layer-0 weights
    for (int it = tid; it < R_IN * 16; it += NTHREADS) {
        int r = it >> 4, c = it & 15;
        int src = sIdx[r];
        float4 v = make_float4(0.f, 0.f, 0.f, 0.f);
        if (src >= 0)
            v = *(const float4*)(xin + ((size_t)b * NPTS + src) * CH + c * 4);
        *(float4*)(smem + OFF_IN + ((size_t)c * R_IN + r) * 16) = v;
    }
#pragma unroll
    for (int k = 0; k < 6; k++)
        ((float4*)sW)[tid + k * NTHREADS] = ((const float4*)wslab)[tid + k * NTHREADS];

#if HAS_TC
    uint32_t tmem;
    asm volatile("ld.shared.b32 %0, [%1];" : "=r"(tmem) : "r"(sbase + OFF_TM));
    FENCE_ASYNC();
    __syncthreads();

    // Warp mapping: tile = w>>3, colhalf = (w>>2)&1, subpartition = w&3 (implicit)
    const int tile  = warp >> 3;
    const int colh  = (warp >> 2) & 1;
    const int myrow = tile * 128 + (warp & 3) * 32 + lane;
    const uint32_t dcol   = tmem + tile * 64 + colh * 32;
    const uint32_t mymbar = mbar + tile * 8;
    const uint32_t otmbar = mbar + (1 - tile) * 8;

    // ================= conv1: IN -> TMEM -> B1 =================
    if (warp == 0 && elect_one())
        issue_conv(sbase + OFF_IN, R_IN, sbase + OFF_W, tmem, mbar);
    {
        float4 wreg[6];  // prefetch layer-1 weights under the MMA
#pragma unroll
        for (int k = 0; k < 6; k++) wreg[k] = ((const float4*)(wslab + 12288))[tid + k * NTHREADS];
        MBAR_WAIT(mymbar, 0);
        TCGEN05_FENCE_AFTER();
        uint32_t rg[32];
        LDTM_X32(rg, dcol);
        TCGEN05_WAIT_LD();
        {
            int r = myrow, p = tile0 - 2 + r;
            bool store = (r < R_B1);
            bool zero = (p < 0) || (p >= NPTS);
            if (store) {
#pragma unroll
                for (int j = 0; j < 8; j++) {
                    int c = colh * 8 + j;
                    float4 v = make_float4(0.f, 0.f, 0.f, 0.f);
                    if (!zero) {
                        float4 bb = *(const float4*)(sBias + c * 4);
                        v.x = fmaxf(__uint_as_float(rg[j * 4 + 0]) + bb.x, 0.f);
                        v.y = fmaxf(__uint_as_float(rg[j * 4 + 1]) + bb.y, 0.f);
                        v.z = fmaxf(__uint_as_float(rg[j * 4 + 2]) + bb.z, 0.f);
                        v.w = fmaxf(__uint_as_float(rg[j * 4 + 3]) + bb.w, 0.f);
                    }
                    *(float4*)(smem + OFF_B1 + ((size_t)c * R_B1 + r) * 16) = v;
                }
            }
        }
        MBAR_WAIT(otmbar, 0);   // both tiles' MMAs done -> safe to overwrite sW
#pragma unroll
        for (int k = 0; k < 6; k++) ((float4*)sW)[tid + k * NTHREADS] = wreg[k];
    }
    TCGEN05_FENCE_BEFORE();
    FENCE_ASYNC();
    __syncthreads();

    // ================= conv2: B1 -> TMEM -> B2 =================
    if (warp == 0 && elect_one())
        issue_conv(sbase + OFF_B1, R_B1, sbase + OFF_W, tmem, mbar);
    {
        float4 wreg[6];
#pragma unroll
        for (int k = 0; k < 6; k++) wreg[k] = ((const float4*)(wslab + 24576))[tid + k * NTHREADS];
        MBAR_WAIT(mymbar, 1);
        TCGEN05_FENCE_AFTER();
        uint32_t rg[32];
        LDTM_X32(rg, dcol);
        TCGEN05_WAIT_LD();
        {
            int r = myrow, p = tile0 - 1 + r;
            bool store = (r < R_B2);
            bool zero = (p < 0) || (p >= NPTS);
            if (store) {
#pragma unroll
                for (int j = 0; j < 8; j++) {
                    int c = colh * 8 + j;
                    float4 v = make_float4(0.f, 0.f, 0.f, 0.f);
                    if (!zero) {
                        float4 bb = *(const float4*)(sBias + 64 + c * 4);
                        v.x = fmaxf(__uint_as_float(rg[j * 4 + 0]) + bb.x, 0.f);
                        v.y = fmaxf(__uint_as_float(rg[j * 4 + 1]) + bb.y, 0.f);
                        v.z = fmaxf(__uint_as_float(rg[j * 4 + 2]) + bb.z, 0.f);
                        v.w = fmaxf(__uint_as_float(rg[j * 4 + 3]) + bb.w, 0.f);
                    }
                    *(float4*)(smem + OFF_B2 + ((size_t)c * R_B2 + r) * 16) = v;
                }
            }
        }
        MBAR_WAIT(otmbar, 1);
#pragma unroll
        for (int k = 0; k < 6; k++) ((float4*)sW)[tid + k * NTHREADS] = wreg[k];
    }
    TCGEN05_FENCE_BEFORE();
    FENCE_ASYNC();
    __syncthreads();

    // ================= conv3: B2 -> TMEM =================
    if (warp == 0 && elect_one())
        issue_conv(sbase + OFF_B2, R_B2, sbase + OFF_W, tmem, mbar);
    MBAR_WAIT(mymbar, 0);
    TCGEN05_FENCE_AFTER();

    // final epilogue: y = relu(residual + h3 + bias2), scatter out[pa[p]] = y[p]
    {
        uint32_t rg[32];
        LDTM_X32(rg, dcol);
        TCGEN05_WAIT_LD();
        int r = myrow;
        bool go = (r < TILE) && (tile0 + r < NPTS);
        if (go) {
            int dst = sIdx[r + 3];
            float* outp = xout + ((size_t)b * NPTS + dst) * CH;
#pragma unroll
            for (int j = 0; j < 8; j++) {
                int c = colh * 8 + j;
                float4 res = *(const float4*)(smem + OFF_IN + ((size_t)c * R_IN + (r + 3)) * 16);
                float4 bb  = *(const float4*)(sBias + 128 + c * 4);
                float4 y;
                y.x = fmaxf(res.x + __uint_as_float(rg[j * 4 + 0]) + bb.x, 0.f);
                y.y = fmaxf(res.y + __uint_as_float(rg[j * 4 + 1]) + bb.y, 0.f);
                y.z = fmaxf(res.z + __uint_as_float(rg[j * 4 + 2]) + bb.z, 0.f);
                y.w = fmaxf(res.w + __uint_as_float(rg[j * 4 + 3]) + bb.w, 0.f);
                *(float4*)(outp + c * 4) = y;
            }
        }
    }
    TCGEN05_FENCE_BEFORE();
    __syncthreads();
    if (warp == 0) TCGEN05_DEALLOC(tmem, 128);

#else // ---- scalar fallback path (compute_103 JIT image only) ----
    __syncthreads();
    conv_scalar(smem, OFF_IN, R_IN, OFF_B1, R_B1, R_B1, tile0 - 2, sW, sBias, tid);
    __syncthreads();
    for (int it = tid; it < 3072; it += NTHREADS)
        ((float4*)sW)[it] = ((const float4*)(wslab + 12288))[it];
    __syncthreads();
    conv_scalar(smem, OFF_B1, R_B1, OFF_B2, R_B2, R_B2, tile0 - 1, sW, sBias + 64, tid);
    __syncthreads();
    for (int it = tid; it < 3072; it += NTHREADS)
        ((float4*)sW)[it] = ((const float4*)(wslab + 24576))[it];
    __syncthreads();
    conv_scalar(smem, OFF_B2, R_B2, OFF_B1, R_B1, TILE, tile0, sW, nullptr, tid);
    __syncthreads();
    for (int it = tid; it < TILE * 16; it += NTHREADS) {
        int r = it >> 4, c = it & 15;
        if (tile0 + r >= NPTS) continue;
        int dst = sIdx[r + 3];
        float4 h   = *(const float4*)(smem + OFF_B1 + ((size_t)c * R_B1 + r) * 16);
        float4 res = *(const float4*)(smem + OFF_IN + ((size_t)c * R_IN + (r + 3)) * 16);
        float4 bb  = *(const float4*)(sBias + 128 + c * 4);
        float4 y;
        y.x = fmaxf(res.x + h.x + bb.x, 0.f);
        y.y = fmaxf(res.y + h.y + bb.y, 0.f);
        y.z = fmaxf(res.z + h.z + bb.z, 0.f);
        y.w = fmaxf(res.w + h.w + bb.w, 0.f);
        *(float4*)(xout + ((size_t)b * NPTS + dst) * CH + c * 4) = y;
    }
#endif
}

// ---------------------------------------------------------------------------
// Launch
// ---------------------------------------------------------------------------
extern "C" void kernel_launch(void* const* d_in, const int* in_sizes, int n_in,
                              void* d_out, int out_size) {
    const float* x      = (const float*)d_in[0];
    const void*  pa1    = d_in[1];
    const void*  pa2    = d_in[3];
    const float* conv_w = (const float*)d_in[5];
    const float* gma    = (const float*)d_in[6];
    const float* bta    = (const float*)d_in[7];
    const float* mean   = (const float*)d_in[8];
    const float* var    = (const float*)d_in[9];

    float* mid;  cudaGetSymbolAddress((void**)&mid,  g_mid);
    float* wt2;  cudaGetSymbolAddress((void**)&wt2,  g_wt2);
    float* bias; cudaGetSymbolAddress((void**)&bias, g_bias);

    cudaFuncSetAttribute(block_kernel, cudaFuncAttributeMaxDynamicSharedMemorySize, SMEM_BYTES);

    detect_idx_kernel<<<1, 256>>>((const unsigned int*)pa1);
    repack_kernel<<<(NBLK * 3 * CH * CH + 255) / 256, 256>>>(conv_w, gma, bta, mean, var);

    dim3 grid(GRID_X, NBATCH);
    block_kernel<<<grid, NTHREADS, SMEM_BYTES>>>(x, mid, pa1, wt2, bias);
    block_kernel<<<grid, NTHREADS, SMEM_BYTES>>>(mid, (float*)d_out, pa2,
                                                 wt2 + 3 * 12288, bias + 3 * CH);
}

// round 7
// speedup vs baseline: 5.3069x; 1.1681x over previous
#include <cuda_runtime.h>
#include <mma.h>
#include <cstdint>
#include <cstddef>

// tcgen05 is arch-SPECIFIC: only on the sm_103a pass; plain compute_103 gets a fallback.
#if defined(__CUDA_ARCH__) && (defined(__CUDA_ARCH_FEAT_SM103_ALL) || defined(__CUDA_ARCH_FEAT_SM100_ALL) || defined(__CUDA_ARCH_FEAT_SM101_ALL))
#define HAS_TC 1
#else
#define HAS_TC 0
#endif

// Problem constants
#define NBATCH   2
#define CH       64
#define NPTS     262144
#define NBLK     2

// Tiling
#define TILE     224
#define R_IN     230
#define R_B1     228
#define R_B2     226
#define NTHREADS 512
#define GRID_X   ((NPTS + TILE - 1) / TILE)   // 1171
#define NWORK    (GRID_X * NBATCH)            // 2342

// SMEM byte offsets. Activation buffers are canonical K-major: addr = c*ROWS*16 + r*16.
// IN0/IN1 ping-pong as gather targets; the current IN doubles as B2 after conv1.
#define OFF_IN0  0
#define OFF_IN1  (R_IN * 256)                    // 58880
#define OFF_B1   (OFF_IN1 + R_IN * 256)          // 117760
#define OFF_W    (OFF_B1 + R_B1 * 256)           // 176128 (48 KB slab: [tap][i16][o row 16B])
#define OFF_BIAS (OFF_W + 49152)                 // 225280 (3 x 64 floats)
#define OFF_IDX0 (OFF_BIAS + 768)                // 226048 (230 ints, padded)
#define OFF_IDX1 (OFF_IDX0 + 960)
#define OFF_TM   (OFF_IDX1 + 960)
#define OFF_MBAR (OFF_TM + 16)                   // two mbarriers
#define SMEM_BYTES (OFF_MBAR + 16)               // 228000

// idesc: D=f32, A=B=tf32, N=64, M=128, K-major, cg1
#define IDESC 0x08100910u

// Device scratch
__device__ float g_mid[(size_t)NBATCH * NPTS * CH];
__device__ float g_wt2[NBLK * 3 * 3 * 16 * 256];   // [bl(6)][tap][i16][o*4+i%4], BN-folded tf32
__device__ float g_bias[NBLK * 3 * CH];
__device__ int   g_is64;

__device__ __forceinline__ uint32_t smem_u32(const void* p) {
    uint32_t a;
    asm("{ .reg .u64 t; cvta.to.shared.u64 t, %1; cvt.u32.u64 %0, t; }" : "=r"(a) : "l"(p));
    return a;
}

// cp.async 16B with zero-fill when invalid (src-size 0)
__device__ __forceinline__ void cp16(uint32_t dst, const void* src, int valid) {
    int sz = valid ? 16 : 0;
    asm volatile("cp.async.cg.shared.global [%0], [%1], 16, %2;" :: "r"(dst), "l"(src), "r"(sz) : "memory");
}
#define CP_COMMIT() asm volatile("cp.async.commit_group;" ::: "memory")
#define CP_WAIT0()  asm volatile("cp.async.wait_group 0;" ::: "memory")

#if HAS_TC
// ---------------------------------------------------------------------------
__device__ __forceinline__ uint32_t elect_one() {
    uint32_t p;
    asm volatile("{\n\t.reg .pred p;\n\telect.sync _|p, 0xFFFFFFFF;\n\tselp.b32 %0, 1, 0, p;\n\t}" : "=r"(p));
    return p;
}
#define TCGEN05_ALLOC(sl, n)  asm volatile("tcgen05.alloc.cta_group::1.sync.aligned.shared::cta.b32 [%0], %1;" :: "r"(sl), "r"((uint32_t)(n)) : "memory")
#define TCGEN05_DEALLOC(t, n) asm volatile("tcgen05.dealloc.cta_group::1.sync.aligned.b32 %0, %1;" :: "r"(t), "r"((uint32_t)(n)))
#define TCGEN05_RELINQ()      asm volatile("tcgen05.relinquish_alloc_permit.cta_group::1.sync.aligned;")
#define TCGEN05_COMMIT(mb)    asm volatile("tcgen05.commit.cta_group::1.mbarrier::arrive::one.shared::cluster.b64 [%0];" :: "r"(mb) : "memory")
#define TCGEN05_WAIT_LD()     asm volatile("tcgen05.wait::ld.sync.aligned;" ::: "memory")
#define TCGEN05_FENCE_AFTER() asm volatile("tcgen05.fence::after_thread_sync;" ::: "memory")
#define TCGEN05_FENCE_BEFORE() asm volatile("tcgen05.fence::before_thread_sync;" ::: "memory")
#define FENCE_ASYNC()         asm volatile("fence.proxy.async.shared::cta;" ::: "memory")
#define MBAR_INIT(mb, n)      asm volatile("mbarrier.init.shared.b64 [%0], %1;" :: "r"(mb), "r"((uint32_t)(n)) : "memory")

#define MBAR_WAIT(mb, ph) do {                                                   \
    uint32_t _m = (mb), _p = (ph), _d;                                           \
    asm volatile("{\n\t.reg .pred p;\n\t"                                        \
        "mbarrier.try_wait.parity.acquire.cta.shared::cta.b64 p, [%1], %2;\n\t"  \
        "selp.b32 %0, 1, 0, p;\n\t}" : "=r"(_d) : "r"(_m), "r"(_p) : "memory");  \
    if (!_d) {                                                                   \
        asm volatile("{\n\t.reg .pred P1;\n\t"                                   \
        "WL_%=:\n\t"                                                             \
        "mbarrier.try_wait.parity.acquire.cta.shared::cta.b64 P1, [%0], %1, 0x989680;\n\t" \
        "@P1 bra.uni WD_%=;\n\t"                                                 \
        "bra.uni WL_%=;\n\t"                                                     \
        "WD_%=:\n\t}" :: "r"(_m), "r"(_p) : "memory");                           \
    }                                                                            \
} while (0)

#define LDTM_X32(r, addr) \
    asm volatile("tcgen05.ld.sync.aligned.32x32b.x32.b32 " \
        "{%0, %1, %2, %3, %4, %5, %6, %7, " \
        " %8, %9, %10, %11, %12, %13, %14, %15, " \
        " %16, %17, %18, %19, %20, %21, %22, %23, " \
        " %24, %25, %26, %27, %28, %29, %30, %31}, [%32];" \
        : "=r"((r)[0]),  "=r"((r)[1]),  "=r"((r)[2]),  "=r"((r)[3]), \
          "=r"((r)[4]),  "=r"((r)[5]),  "=r"((r)[6]),  "=r"((r)[7]), \
          "=r"((r)[8]),  "=r"((r)[9]),  "=r"((r)[10]), "=r"((r)[11]), \
          "=r"((r)[12]), "=r"((r)[13]), "=r"((r)[14]), "=r"((r)[15]), \
          "=r"((r)[16]), "=r"((r)[17]), "=r"((r)[18]), "=r"((r)[19]), \
          "=r"((r)[20]), "=r"((r)[21]), "=r"((r)[22]), "=r"((r)[23]), \
          "=r"((r)[24]), "=r"((r)[25]), "=r"((r)[26]), "=r"((r)[27]), \
          "=r"((r)[28]), "=r"((r)[29]), "=r"((r)[30]), "=r"((r)[31]) \
        : "r"(addr))

__device__ __forceinline__ void mma_tf32(uint32_t d, uint64_t ad, uint64_t bd, uint32_t en) {
    asm volatile("{\n\t.reg .pred p;\n\tsetp.ne.u32 p, %4, 0;\n\t"
        "tcgen05.mma.cta_group::1.kind::tf32 [%0], %1, %2, %3, {%5, %5, %5, %5}, p;\n\t}"
        :: "r"(d), "l"(ad), "l"(bd), "r"(IDESC), "r"(en), "r"(0u) : "memory");
}

__device__ __forceinline__ uint64_t make_desc(uint32_t addr, uint32_t lbo, uint32_t sbo) {
    uint64_t d = (uint64_t)((addr >> 4) & 0x3FFF);
    d |= (uint64_t)(lbo & 0x3FFF) << 16;
    d |= (uint64_t)(sbo & 0x3FFF) << 32;
    d |= (uint64_t)1 << 46;
    return d;
}

// One conv layer, per-M-tile commit: tile0 -> mbar0, tile1 -> mbar1.
__device__ __forceinline__ void issue_conv(uint32_t aAddr, int aLBO, uint32_t wAddr,
                                           uint32_t tmem, uint32_t mbar) {
    uint64_t ab = make_desc(aAddr, aLBO, 8);
    uint64_t bb = make_desc(wAddr, 64, 8);
#pragma unroll
    for (int T = 0; T < 2; T++) {
        uint32_t en = 0;
#pragma unroll
        for (int tap = 0; tap < 3; tap++)
#pragma unroll
            for (int ks = 0; ks < 8; ks++) {
                mma_tf32(tmem + T * 64,
                         ab + (uint64_t)(T * 128 + tap + 2 * ks * aLBO),
                         bb + (uint64_t)(tap * 1024 + 2 * ks * 64), en);
                en = 1;
            }
        TCGEN05_COMMIT(mbar + T * 8);
    }
}
#else  // !HAS_TC -----------------------------------------------------------
__device__ void conv_scalar(char* smem, int offIn, int rowsIn, int offOut, int rowsOut,
                            int live, int posBase, const float* sW,
                            const float* sBiasL, int tid) {
    for (int r = tid; r < live; r += NTHREADS) {
        float acc[CH];
#pragma unroll
        for (int o = 0; o < CH; o++) acc[o] = 0.f;
        bool zero = (posBase + r < 0) || (posBase + r >= NPTS);
        if (!zero) {
            for (int tap = 0; tap < 3; tap++)
                for (int ci = 0; ci < 16; ci++) {
                    const float* inp = (const float*)(smem + offIn + ((size_t)ci * rowsIn + r + tap) * 16);
                    float x0 = inp[0], x1 = inp[1], x2 = inp[2], x3 = inp[3];
                    const float* wp = sW + tap * 4096 + ci * 256;
                    for (int o = 0; o < CH; o++)
                        acc[o] += x0 * wp[o * 4] + x1 * wp[o * 4 + 1]
                                + x2 * wp[o * 4 + 2] + x3 * wp[o * 4 + 3];
                }
        }
        for (int ci = 0; ci < 16; ci++) {
            float4 v = make_float4(0.f, 0.f, 0.f, 0.f);
            if (!zero) {
                if (sBiasL) {
                    v.x = fmaxf(acc[ci * 4 + 0] + sBiasL[ci * 4 + 0], 0.f);
                    v.y = fmaxf(acc[ci * 4 + 1] + sBiasL[ci * 4 + 1], 0.f);
                    v.z = fmaxf(acc[ci * 4 + 2] + sBiasL[ci * 4 + 2], 0.f);
                    v.w = fmaxf(acc[ci * 4 + 3] + sBiasL[ci * 4 + 3], 0.f);
                } else {
                    v = make_float4(acc[ci * 4], acc[ci * 4 + 1], acc[ci * 4 + 2], acc[ci * 4 + 3]);
                }
            }
            *(float4*)(smem + offOut + ((size_t)ci * rowsOut + r) * 16) = v;
        }
    }
}
#endif // HAS_TC

// ---------------------------------------------------------------------------
// Prep kernels
// ---------------------------------------------------------------------------
__global__ void detect_idx_kernel(const unsigned int* __restrict__ w) {
    __shared__ int any;
    if (threadIdx.x == 0) any = 0;
    __syncthreads();
    int local = 0;
    for (int i = threadIdx.x; i < 2048; i += blockDim.x)
        if (w[2 * i + 1] != 0u) local = 1;
    if (local) atomicOr(&any, 1);
    __syncthreads();
    if (threadIdx.x == 0) g_is64 = any ? 0 : 1;
}

__global__ void repack_kernel(const float* __restrict__ w,
                              const float* __restrict__ gm,
                              const float* __restrict__ bt,
                              const float* __restrict__ mn,
                              const float* __restrict__ vr) {
    int idx = blockIdx.x * blockDim.x + threadIdx.x;
    if (idx >= NBLK * 3 * CH * CH) return;
    int i  = idx & 63;
    int o  = (idx >> 6) & 63;
    int bl = idx >> 12;
    float scale = gm[bl * CH + o] * rsqrtf(vr[bl * CH + o] + 1e-5f);
#pragma unroll
    for (int t = 0; t < 3; t++) {
        float val = w[(((size_t)bl * CH + o) * CH + i) * 3 + t] * scale;
        g_wt2[(size_t)bl * 12288 + ((t * 16 + (i >> 2)) * 256) + o * 4 + (i & 3)] =
            nvcuda::wmma::__float_to_tf32(val);
    }
    if (i == 0)
        g_bias[bl * CH + o] = bt[bl * CH + o] - mn[bl * CH + o] * scale;
}

// ---------------------------------------------------------------------------
// Persistent fused block kernel: loop over tiles; per tile
// gather(prefetched) -> conv x3 (TMEM) -> residual -> scatter; cp.async
// prefetches the NEXT tile's gather under the current tile's MMAs.
// ---------------------------------------------------------------------------
__global__ __launch_bounds__(NTHREADS, 1)
void block_kernel(const float* __restrict__ xin, float* __restrict__ xout,
                  const void* __restrict__ paPtr,
                  const float* __restrict__ wslab, const float* __restrict__ bias) {
    extern __shared__ char smem[];
    const int tid  = threadIdx.x;
    const int warp = tid >> 5;
    const int lane = tid & 31;
    const int is64 = g_is64;

    const uint32_t sbase = smem_u32(smem);
    float* sBias = (float*)(smem + OFF_BIAS);
    float* sW    = (float*)(smem + OFF_W);

    const int inOff[2]  = {OFF_IN0, OFF_IN1};
    const int idxOff[2] = {OFF_IDX0, OFF_IDX1};

#if HAS_TC
    const uint32_t mbar = sbase + OFF_MBAR;
    if (tid == 0) { MBAR_INIT(mbar, 1); MBAR_INIT(mbar + 8, 1); }
    if (warp == 0) {
        TCGEN05_ALLOC(sbase + OFF_TM, 128);
        TCGEN05_RELINQ();
    }
#endif

    // bias + layer-0 weights (once)
    if (tid < 3 * CH) sBias[tid] = bias[tid];
#pragma unroll
    for (int k = 0; k < 6; k++)
        ((float4*)sW)[tid + k * NTHREADS] = ((const float4*)wslab)[tid + k * NTHREADS];

    // ---- prologue: idx + gather for the first work ----
    int work = blockIdx.x;
    {
        int b0 = work / GRID_X, t0 = (work % GRID_X) * TILE;
        int* sIdxC = (int*)(smem + idxOff[0]);
        for (int r = tid; r < R_IN; r += NTHREADS) {
            int p = t0 - 3 + r;
            int v = -1;
            if (p >= 0 && p < NPTS) {
                size_t gp = (size_t)b0 * NPTS + p;
                v = is64 ? (int)((const long long*)paPtr)[gp] : ((const int*)paPtr)[gp];
            }
            sIdxC[r] = v;
        }
        __syncthreads();
        const float* xb = xin + (size_t)b0 * NPTS * CH;
        for (int it = tid; it < R_IN * 16; it += NTHREADS) {
            int r = it >> 4, c = it & 15;
            int src = sIdxC[r];
            cp16(sbase + inOff[0] + (uint32_t)(c * R_IN + r) * 16,
                 (src >= 0) ? (const void*)(xb + (size_t)src * CH + c * 4) : (const void*)xin,
                 src >= 0);
        }
        CP_COMMIT();
    }

#if HAS_TC
    uint32_t tmem;
    __syncthreads();
    asm volatile("ld.shared.b32 %0, [%1];" : "=r"(tmem) : "r"(sbase + OFF_TM));

    // Warp mapping: tile = w>>3, colhalf = (w>>2)&1, subpartition = w&3
    const int mtile = warp >> 3;
    const int colh  = (warp >> 2) & 1;
    const int myrow = mtile * 128 + (warp & 3) * 32 + lane;
    const uint32_t dcol   = tmem + mtile * 64 + colh * 32;
    const uint32_t mymbar = mbar + mtile * 8;
    const uint32_t otmbar = mbar + (1 - mtile) * 8;

    int ph = 0;
    int cur = 0;
    for (; work < NWORK; work += gridDim.x, cur ^= 1) {
        const int b     = work / GRID_X;
        const int tile0 = (work % GRID_X) * TILE;
        const int wnext = work + gridDim.x;
        const int nxt   = cur ^ 1;
        const uint32_t IN = sbase + inOff[cur];
        char* INp = smem + inOff[cur];
        int* sIdxC = (int*)(smem + idxOff[cur]);
        int* sIdxN = (int*)(smem + idxOff[nxt]);

        // current gather complete; make visible to async proxy
        CP_WAIT0();
        TCGEN05_FENCE_BEFORE();
        FENCE_ASYNC();
        __syncthreads();

        // ======== conv1: IN -> TMEM -> B1 ========
        if (warp == 0 && elect_one())
            issue_conv(IN, R_IN, sbase + OFF_W, tmem, mbar);

        // under the MMA: load next tile's permutation indices + prefetch W1
        if (wnext < NWORK) {
            int bn = wnext / GRID_X, tn = (wnext % GRID_X) * TILE;
            for (int r = tid; r < R_IN; r += NTHREADS) {
                int p = tn - 3 + r;
                int v = -1;
                if (p >= 0 && p < NPTS) {
                    size_t gp = (size_t)bn * NPTS + p;
                    v = is64 ? (int)((const long long*)paPtr)[gp] : ((const int*)paPtr)[gp];
                }
                sIdxN[r] = v;
            }
        }
        float4 wreg[6];
#pragma unroll
        for (int k = 0; k < 6; k++) wreg[k] = ((const float4*)(wslab + 12288))[tid + k * NTHREADS];

        MBAR_WAIT(mymbar, ph);
        TCGEN05_FENCE_AFTER();
        {
            uint32_t rg[32];
            LDTM_X32(rg, dcol);
            TCGEN05_WAIT_LD();
            int r = myrow, p = tile0 - 2 + r;
            if (r < R_B1) {
                bool zero = (p < 0) || (p >= NPTS);
#pragma unroll
                for (int j = 0; j < 8; j++) {
                    int c = colh * 8 + j;
                    float4 v = make_float4(0.f, 0.f, 0.f, 0.f);
                    if (!zero) {
                        float4 bb = *(const float4*)(sBias + c * 4);
                        v.x = fmaxf(__uint_as_float(rg[j * 4 + 0]) + bb.x, 0.f);
                        v.y = fmaxf(__uint_as_float(rg[j * 4 + 1]) + bb.y, 0.f);
                        v.z = fmaxf(__uint_as_float(rg[j * 4 + 2]) + bb.z, 0.f);
                        v.w = fmaxf(__uint_as_float(rg[j * 4 + 3]) + bb.w, 0.f);
                    }
                    *(float4*)(smem + OFF_B1 + ((size_t)c * R_B1 + r) * 16) = v;
                }
            }
        }
        MBAR_WAIT(otmbar, ph);     // both tiles done with sW
#pragma unroll
        for (int k = 0; k < 6; k++) ((float4*)sW)[tid + k * NTHREADS] = wreg[k];
        ph ^= 1;
        TCGEN05_FENCE_BEFORE();
        FENCE_ASYNC();
        __syncthreads();

        // ======== conv2: B1 -> TMEM -> B2(=IN) ========
        if (warp == 0 && elect_one())
            issue_conv(sbase + OFF_B1, R_B1, sbase + OFF_W, tmem, mbar);

        // under the MMA: issue next tile's gather (into IN[nxt]) + prefetch W2
        if (wnext < NWORK) {
            int bn = wnext / GRID_X;
            const float* xb = xin + (size_t)bn * NPTS * CH;
            for (int it = tid; it < R_IN * 16; it += NTHREADS) {
                int r = it >> 4, c = it & 15;
                int src = sIdxN[r];
                cp16(sbase + inOff[nxt] + (uint32_t)(c * R_IN + r) * 16,
                     (src >= 0) ? (const void*)(xb + (size_t)src * CH + c * 4) : (const void*)xin,
                     src >= 0);
            }
        }
        CP_COMMIT();
#pragma unroll
        for (int k = 0; k < 6; k++) wreg[k] = ((const float4*)(wslab + 24576))[tid + k * NTHREADS];

        MBAR_WAIT(mymbar, ph);
        TCGEN05_FENCE_AFTER();
        uint32_t rg2[32];
        LDTM_X32(rg2, dcol);
        TCGEN05_WAIT_LD();
        MBAR_WAIT(otmbar, ph);     // both tiles done reading B1 and sW
        ph ^= 1;
        // residual copy IN[rows r+3] -> B1[rows r] (own row), before B2 overwrites IN
        if (myrow < TILE) {
#pragma unroll
            for (int j = 0; j < 8; j++) {
                int c = colh * 8 + j;
                float4 v = *(const float4*)(INp + ((size_t)c * R_IN + (myrow + 3)) * 16);
                *(float4*)(smem + OFF_B1 + ((size_t)c * R_B1 + myrow) * 16) = v;
            }
        }
        __syncthreads();           // residual reads complete before B2 writes
        {
            int r = myrow, p = tile0 - 1 + r;
            if (r < R_B2) {
                bool zero = (p < 0) || (p >= NPTS);
#pragma unroll
                for (int j = 0; j < 8; j++) {
                    int c = colh * 8 + j;
                    float4 v = make_float4(0.f, 0.f, 0.f, 0.f);
                    if (!zero) {
                        float4 bb = *(const float4*)(sBias + 64 + c * 4);
                        v.x = fmaxf(__uint_as_float(rg2[j * 4 + 0]) + bb.x, 0.f);
                        v.y = fmaxf(__uint_as_float(rg2[j * 4 + 1]) + bb.y, 0.f);
                        v.z = fmaxf(__uint_as_float(rg2[j * 4 + 2]) + bb.z, 0.f);
                        v.w = fmaxf(__uint_as_float(rg2[j * 4 + 3]) + bb.w, 0.f);
                    }
                    *(float4*)(INp + ((size_t)c * R_B2 + r) * 16) = v;
                }
            }
        }
#pragma unroll
        for (int k = 0; k < 6; k++) ((float4*)sW)[tid + k * NTHREADS] = wreg[k];
        TCGEN05_FENCE_BEFORE();
        FENCE_ASYNC();
        __syncthreads();

        // ======== conv3: B2(=IN) -> TMEM ========
        if (warp == 0 && elect_one())
            issue_conv(IN, R_B2, sbase + OFF_W, tmem, mbar);

        // prefetch next tile's W0 under the MMA
#pragma unroll
        for (int k = 0; k < 6; k++) wreg[k] = ((const float4*)wslab)[tid + k * NTHREADS];

        MBAR_WAIT(mymbar, ph);
        TCGEN05_FENCE_AFTER();
        {
            uint32_t rg[32];
            LDTM_X32(rg, dcol);
            TCGEN05_WAIT_LD();
            int r = myrow;
            bool go = (r < TILE) && (tile0 + r < NPTS);
            if (go) {
                int dst = sIdxC[r + 3];
                float* outp = xout + ((size_t)b * NPTS + dst) * CH;
#pragma unroll
                for (int j = 0; j < 8; j++) {
                    int c = colh * 8 + j;
                    float4 res = *(const float4*)(smem + OFF_B1 + ((size_t)c * R_B1 + r) * 16);
                    float4 bb  = *(const float4*)(sBias + 128 + c * 4);
                    float4 y;
                    y.x = fmaxf(res.x + __uint_as_float(rg[j * 4 + 0]) + bb.x, 0.f);
                    y.y = fmaxf(res.y + __uint_as_float(rg[j * 4 + 1]) + bb.y, 0.f);
                    y.z = fmaxf(res.z + __uint_as_float(rg[j * 4 + 2]) + bb.z, 0.f);
                    y.w = fmaxf(res.w + __uint_as_float(rg[j * 4 + 3]) + bb.w, 0.f);
                    *(float4*)(outp + c * 4) = y;
                }
            }
        }
        MBAR_WAIT(otmbar, ph);
        ph ^= 1;
#pragma unroll
        for (int k = 0; k < 6; k++) ((float4*)sW)[tid + k * NTHREADS] = wreg[k];
        TCGEN05_FENCE_BEFORE();
        __syncthreads();
    }
    if (warp == 0) TCGEN05_DEALLOC(tmem, 128);

#else // ---- scalar fallback (compute_103 JIT image only): persistent, unpipelined ----
    int cur = 0;
    for (; work < NWORK; work += gridDim.x) {
        const int b     = work / GRID_X;
        const int tile0 = (work % GRID_X) * TILE;
        int* sIdxC = (int*)(smem + idxOff[0]);
        CP_WAIT0();
        __syncthreads();
        if (cur) {  // reload idx+gather for this work (prologue covered the first)
            for (int r = tid; r < R_IN; r += NTHREADS) {
                int p = tile0 - 3 + r;
                int v = -1;
                if (p >= 0 && p < NPTS) {
                    size_t gp = (size_t)b * NPTS + p;
                    v = is64 ? (int)((const long long*)paPtr)[gp] : ((const int*)paPtr)[gp];
                }
                sIdxC[r] = v;
            }
            __syncthreads();
            const float* xb = xin + (size_t)b * NPTS * CH;
            for (int it = tid; it < R_IN * 16; it += NTHREADS) {
                int r = it >> 4, c = it & 15;
                int src = sIdxC[r];
                float4 v = make_float4(0.f, 0.f, 0.f, 0.f);
                if (src >= 0) v = *(const float4*)(xb + (size_t)src * CH + c * 4);
                *(float4*)(smem + OFF_IN0 + ((size_t)c * R_IN + r) * 16) = v;
            }
            __syncthreads();
        } else {
            cur = 1;
            __syncthreads();
        }
        conv_scalar(smem, OFF_IN0, R_IN, OFF_B1, R_B1, R_B1, tile0 - 2, sW, sBias, tid);
        __syncthreads();
        for (int it = tid; it < 3072; it += NTHREADS)
            ((float4*)sW)[it] = ((const float4*)(wslab + 12288))[it];
        __syncthreads();
        conv_scalar(smem, OFF_B1, R_B1, OFF_IN1, R_B2, R_B2, tile0 - 1, sW, sBias + 64, tid);
        __syncthreads();
        for (int it = tid; it < 3072; it += NTHREADS)
            ((float4*)sW)[it] = ((const float4*)(wslab + 24576))[it];
        __syncthreads();
        conv_scalar(smem, OFF_IN1, R_B2, OFF_B1, R_B1, TILE, tile0, sW, nullptr, tid);
        __syncthreads();
        for (int it = tid; it < TILE * 16; it += NTHREADS) {
            int r = it >> 4, c = it & 15;
            if (tile0 + r >= NPTS) continue;
            int dst = sIdxC[r + 3];
            float4 h   = *(const float4*)(smem + OFF_B1 + ((size_t)c * R_B1 + r) * 16);
            float4 res = *(const float4*)(smem + OFF_IN0 + ((size_t)c * R_IN + (r + 3)) * 16);
            float4 bb  = *(const float4*)(sBias + 128 + c * 4);
            float4 y;
            y.x = fmaxf(res.x + h.x + bb.x, 0.f);
            y.y = fmaxf(res.y + h.y + bb.y, 0.f);
            y.z = fmaxf(res.z + h.z + bb.z, 0.f);
            y.w = fmaxf(res.w + h.w + bb.w, 0.f);
            *(float4*)(xout + ((size_t)b * NPTS + dst) * CH + c * 4) = y;
        }
        __syncthreads();
        for (int it = tid; it < 3072; it += NTHREADS)
            ((float4*)sW)[it] = ((const float4*)wslab)[it];
        __syncthreads();
    }
#endif
}

// ---------------------------------------------------------------------------
// Launch
// ---------------------------------------------------------------------------
extern "C" void kernel_launch(void* const* d_in, const int* in_sizes, int n_in,
                              void* d_out, int out_size) {
    const float* x      = (const float*)d_in[0];
    const void*  pa1    = d_in[1];
    const void*  pa2    = d_in[3];
    const float* conv_w = (const float*)d_in[5];
    const float* gma    = (const float*)d_in[6];
    const float* bta    = (const float*)d_in[7];
    const float* mean   = (const float*)d_in[8];
    const float* var    = (const float*)d_in[9];

    float* mid;  cudaGetSymbolAddress((void**)&mid,  g_mid);
    float* wt2;  cudaGetSymbolAddress((void**)&wt2,  g_wt2);
    float* bias; cudaGetSymbolAddress((void**)&bias, g_bias);

    int nsm = 148;
    cudaDeviceGetAttribute(&nsm, cudaDevAttrMultiProcessorCount, 0);

    cudaFuncSetAttribute(block_kernel, cudaFuncAttributeMaxDynamicSharedMemorySize, SMEM_BYTES);

    detect_idx_kernel<<<1, 256>>>((const unsigned int*)pa1);
    repack_kernel<<<(NBLK * 3 * CH * CH + 255) / 256, 256>>>(conv_w, gma, bta, mean, var);

    block_kernel<<<nsm, NTHREADS, SMEM_BYTES>>>(x, mid, pa1, wt2, bias);
    block_kernel<<<nsm, NTHREADS, SMEM_BYTES>>>(mid, (float*)d_out, pa2,
                                                wt2 + 3 * 12288, bias + 3 * CH);
}

// round 8
// speedup vs baseline: 6.0808x; 1.1458x over previous
#include <cuda_runtime.h>
#include <mma.h>
#include <cstdint>
#include <cstddef>

// tcgen05 is arch-SPECIFIC: only on the sm_103a pass; plain compute_103 gets a fallback.
#if defined(__CUDA_ARCH__) && (defined(__CUDA_ARCH_FEAT_SM103_ALL) || defined(__CUDA_ARCH_FEAT_SM100_ALL) || defined(__CUDA_ARCH_FEAT_SM101_ALL))
#define HAS_TC 1
#else
#define HAS_TC 0
#endif

// Problem constants
#define NBATCH   2
#define CH       64
#define NPTS     262144
#define NBLK     2

// Tiling
#define TILE     224
#define R_IN     230
#define R_B1     228
#define R_B2     226
#define NTHREADS 512
#define GRID_X   ((NPTS + TILE - 1) / TILE)   // 1171
#define NWORK    (GRID_X * NBATCH)            // 2342

// SMEM byte offsets. Activation buffers canonical K-major: addr = c*ROWS*16 + r*16.
// IN0/IN1 ping-pong gather targets (IN preserved through the tile for the residual);
// B1 holds conv1 output, then is reused for conv2 output (B2) once conv2 MMAs drain.
#define OFF_IN0   0
#define OFF_IN1   (R_IN * 256)                  // 58880
#define OFF_B1    (OFF_IN1 + R_IN * 256)        // 117760
#define OFF_W     (OFF_B1 + R_B1 * 256)         // 176128 (48 KB: [tap][i16][o row 16B])
#define OFF_BIAS  (OFF_W + 49152)               // 225280
#define OFF_IDXG0 (OFF_BIAS + 768)              // 226048 (230 ints gather idx)
#define OFF_IDXG1 (OFF_IDXG0 + 960)             // 227008
#define OFF_IDXS0 (OFF_IDXG1 + 960)             // 227968 (224 ints scatter idx)
#define OFF_IDXS1 (OFF_IDXS0 + 896)             // 228864
#define OFF_TM    (OFF_IDXS1 + 896)             // 229760
#define OFF_MBAR  (OFF_TM + 16)                 // 229776
#define OFF_WORK  (OFF_MBAR + 16)               // 229792
#define SMEM_BYTES (OFF_WORK + 16)              // 229808 (< 232448 max)

// idesc: D=f32, A=B=tf32, N=64, M=128, K-major, cg1
#define IDESC 0x08100910u

// Device scratch
__device__ float g_mid[(size_t)NBATCH * NPTS * CH];
__device__ float g_wt2[NBLK * 3 * 3 * 16 * 256];   // [bl(6)][tap][i16][o*4+i%4], BN-folded tf32
__device__ float g_bias[NBLK * 3 * CH];
__device__ int   g_comp[NBATCH * NPTS];            // composed scatter idx for block 1
__device__ int   g_ctr[2];                         // work-stealing counters
__device__ int   g_is64;

__device__ __forceinline__ uint32_t smem_u32(const void* p) {
    uint32_t a;
    asm("{ .reg .u64 t; cvta.to.shared.u64 t, %1; cvt.u32.u64 %0, t; }" : "=r"(a) : "l"(p));
    return a;
}

// cp.async 16B with zero-fill when invalid (src-size 0)
__device__ __forceinline__ void cp16(uint32_t dst, const void* src, int valid) {
    int sz = valid ? 16 : 0;
    asm volatile("cp.async.cg.shared.global [%0], [%1], 16, %2;" :: "r"(dst), "l"(src), "r"(sz) : "memory");
}
#define CP_COMMIT() asm volatile("cp.async.commit_group;" ::: "memory")
#define CP_WAIT0()  asm volatile("cp.async.wait_group 0;" ::: "memory")

#if HAS_TC
// ---------------------------------------------------------------------------
__device__ __forceinline__ uint32_t elect_one() {
    uint32_t p;
    asm volatile("{\n\t.reg .pred p;\n\telect.sync _|p, 0xFFFFFFFF;\n\tselp.b32 %0, 1, 0, p;\n\t}" : "=r"(p));
    return p;
}
#define TCGEN05_ALLOC(sl, n)  asm volatile("tcgen05.alloc.cta_group::1.sync.aligned.shared::cta.b32 [%0], %1;" :: "r"(sl), "r"((uint32_t)(n)) : "memory")
#define TCGEN05_DEALLOC(t, n) asm volatile("tcgen05.dealloc.cta_group::1.sync.aligned.b32 %0, %1;" :: "r"(t), "r"((uint32_t)(n)))
#define TCGEN05_RELINQ()      asm volatile("tcgen05.relinquish_alloc_permit.cta_group::1.sync.aligned;")
#define TCGEN05_COMMIT(mb)    asm volatile("tcgen05.commit.cta_group::1.mbarrier::arrive::one.shared::cluster.b64 [%0];" :: "r"(mb) : "memory")
#define TCGEN05_WAIT_LD()     asm volatile("tcgen05.wait::ld.sync.aligned;" ::: "memory")
#define TCGEN05_FENCE_AFTER() asm volatile("tcgen05.fence::after_thread_sync;" ::: "memory")
#define TCGEN05_FENCE_BEFORE() asm volatile("tcgen05.fence::before_thread_sync;" ::: "memory")
#define FENCE_ASYNC()         asm volatile("fence.proxy.async.shared::cta;" ::: "memory")
#define MBAR_INIT(mb, n)      asm volatile("mbarrier.init.shared.b64 [%0], %1;" :: "r"(mb), "r"((uint32_t)(n)) : "memory")

#define MBAR_WAIT(mb, ph) do {                                                   \
    uint32_t _m = (mb), _p = (ph), _d;                                           \
    asm volatile("{\n\t.reg .pred p;\n\t"                                        \
        "mbarrier.try_wait.parity.acquire.cta.shared::cta.b64 p, [%1], %2;\n\t"  \
        "selp.b32 %0, 1, 0, p;\n\t}" : "=r"(_d) : "r"(_m), "r"(_p) : "memory");  \
    if (!_d) {                                                                   \
        asm volatile("{\n\t.reg .pred P1;\n\t"                                   \
        "WL_%=:\n\t"                                                             \
        "mbarrier.try_wait.parity.acquire.cta.shared::cta.b64 P1, [%0], %1, 0x989680;\n\t" \
        "@P1 bra.uni WD_%=;\n\t"                                                 \
        "bra.uni WL_%=;\n\t"                                                     \
        "WD_%=:\n\t}" :: "r"(_m), "r"(_p) : "memory");                           \
    }                                                                            \
} while (0)

#define LDTM_X32(r, addr) \
    asm volatile("tcgen05.ld.sync.aligned.32x32b.x32.b32 " \
        "{%0, %1, %2, %3, %4, %5, %6, %7, " \
        " %8, %9, %10, %11, %12, %13, %14, %15, " \
        " %16, %17, %18, %19, %20, %21, %22, %23, " \
        " %24, %25, %26, %27, %28, %29, %30, %31}, [%32];" \
        : "=r"((r)[0]),  "=r"((r)[1]),  "=r"((r)[2]),  "=r"((r)[3]), \
          "=r"((r)[4]),  "=r"((r)[5]),  "=r"((r)[6]),  "=r"((r)[7]), \
          "=r"((r)[8]),  "=r"((r)[9]),  "=r"((r)[10]), "=r"((r)[11]), \
          "=r"((r)[12]), "=r"((r)[13]), "=r"((r)[14]), "=r"((r)[15]), \
          "=r"((r)[16]), "=r"((r)[17]), "=r"((r)[18]), "=r"((r)[19]), \
          "=r"((r)[20]), "=r"((r)[21]), "=r"((r)[22]), "=r"((r)[23]), \
          "=r"((r)[24]), "=r"((r)[25]), "=r"((r)[26]), "=r"((r)[27]), \
          "=r"((r)[28]), "=r"((r)[29]), "=r"((r)[30]), "=r"((r)[31]) \
        : "r"(addr))

__device__ __forceinline__ void mma_tf32(uint32_t d, uint64_t ad, uint64_t bd, uint32_t en) {
    asm volatile("{\n\t.reg .pred p;\n\tsetp.ne.u32 p, %4, 0;\n\t"
        "tcgen05.mma.cta_group::1.kind::tf32 [%0], %1, %2, %3, {%5, %5, %5, %5}, p;\n\t}"
        :: "r"(d), "l"(ad), "l"(bd), "r"(IDESC), "r"(en), "r"(0u) : "memory");
}

__device__ __forceinline__ uint64_t make_desc(uint32_t addr, uint32_t lbo, uint32_t sbo) {
    uint64_t d = (uint64_t)((addr >> 4) & 0x3FFF);
    d |= (uint64_t)(lbo & 0x3FFF) << 16;
    d |= (uint64_t)(sbo & 0x3FFF) << 32;
    d |= (uint64_t)1 << 46;
    return d;
}

// One conv layer, per-M-tile commit: tile0 -> mbar0, tile1 -> mbar1.
__device__ __forceinline__ void issue_conv(uint32_t aAddr, int aLBO, uint32_t wAddr,
                                           uint32_t tmem, uint32_t mbar) {
    uint64_t ab = make_desc(aAddr, aLBO, 8);
    uint64_t bb = make_desc(wAddr, 64, 8);
#pragma unroll
    for (int T = 0; T < 2; T++) {
        uint32_t en = 0;
#pragma unroll
        for (int tap = 0; tap < 3; tap++)
#pragma unroll
            for (int ks = 0; ks < 8; ks++) {
                mma_tf32(tmem + T * 64,
                         ab + (uint64_t)(T * 128 + tap + 2 * ks * aLBO),
                         bb + (uint64_t)(tap * 1024 + 2 * ks * 64), en);
                en = 1;
            }
        TCGEN05_COMMIT(mbar + T * 8);
    }
}
#else  // !HAS_TC -----------------------------------------------------------
__device__ void conv_scalar(char* smem, int offIn, int rowsIn, int offOut, int rowsOut,
                            int live, int posBase, const float* sW,
                            const float* sBiasL, int tid) {
    for (int r = tid; r < live; r += NTHREADS) {
        float acc[CH];
#pragma unroll
        for (int o = 0; o < CH; o++) acc[o] = 0.f;
        bool zero = (posBase + r < 0) || (posBase + r >= NPTS);
        if (!zero) {
            for (int tap = 0; tap < 3; tap++)
                for (int ci = 0; ci < 16; ci++) {
                    const float* inp = (const float*)(smem + offIn + ((size_t)ci * rowsIn + r + tap) * 16);
                    float x0 = inp[0], x1 = inp[1], x2 = inp[2], x3 = inp[3];
                    const float* wp = sW + tap * 4096 + ci * 256;
                    for (int o = 0; o < CH; o++)
                        acc[o] += x0 * wp[o * 4] + x1 * wp[o * 4 + 1]
                                + x2 * wp[o * 4 + 2] + x3 * wp[o * 4 + 3];
                }
        }
        for (int ci = 0; ci < 16; ci++) {
            float4 v = make_float4(0.f, 0.f, 0.f, 0.f);
            if (!zero) {
                if (sBiasL) {
                    v.x = fmaxf(acc[ci * 4 + 0] + sBiasL[ci * 4 + 0], 0.f);
                    v.y = fmaxf(acc[ci * 4 + 1] + sBiasL[ci * 4 + 1], 0.f);
                    v.z = fmaxf(acc[ci * 4 + 2] + sBiasL[ci * 4 + 2], 0.f);
                    v.w = fmaxf(acc[ci * 4 + 3] + sBiasL[ci * 4 + 3], 0.f);
                } else {
                    v = make_float4(acc[ci * 4], acc[ci * 4 + 1], acc[ci * 4 + 2], acc[ci * 4 + 3]);
                }
            }
            *(float4*)(smem + offOut + ((size_t)ci * rowsOut + r) * 16) = v;
        }
    }
}
#endif // HAS_TC

// ---------------------------------------------------------------------------
// Prep kernels
// ---------------------------------------------------------------------------
__global__ void detect_idx_kernel(const unsigned int* __restrict__ w) {
    __shared__ int any;
    if (threadIdx.x == 0) { any = 0; g_ctr[0] = 0; g_ctr[1] = 0; }
    __syncthreads();
    int local = 0;
    for (int i = threadIdx.x; i < 2048; i += blockDim.x)
        if (w[2 * i + 1] != 0u) local = 1;
    if (local) atomicOr(&any, 1);
    __syncthreads();
    if (threadIdx.x == 0) g_is64 = any ? 0 : 1;
}

__global__ void repack_kernel(const float* __restrict__ w,
                              const float* __restrict__ gm,
                              const float* __restrict__ bt,
                              const float* __restrict__ mn,
                              const float* __restrict__ vr) {
    int idx = blockIdx.x * blockDim.x + threadIdx.x;
    if (idx >= NBLK * 3 * CH * CH) return;
    int i  = idx & 63;
    int o  = (idx >> 6) & 63;
    int bl = idx >> 12;
    float scale = gm[bl * CH + o] * rsqrtf(vr[bl * CH + o] + 1e-5f);
#pragma unroll
    for (int t = 0; t < 3; t++) {
        float val = w[(((size_t)bl * CH + o) * CH + i) * 3 + t] * scale;
        g_wt2[(size_t)bl * 12288 + ((t * 16 + (i >> 2)) * 256) + o * 4 + (i & 3)] =
            nvcuda::wmma::__float_to_tf32(val);
    }
    if (i == 0)
        g_bias[bl * CH + o] = bt[bl * CH + o] - mn[bl * CH + o] * scale;
}

// comp[b][p] = re2[b][ pa1[b][p] ]  (block1 scatters mid into block2-gather order)
__global__ void compose_kernel(const void* __restrict__ pa1, const void* __restrict__ re2) {
    int idx = blockIdx.x * blockDim.x + threadIdx.x;
    if (idx >= NBATCH * NPTS) return;
    int b = idx / NPTS;
    int is64 = g_is64;
    long long v1 = is64 ? ((const long long*)pa1)[idx] : (long long)((const int*)pa1)[idx];
    size_t j = (size_t)b * NPTS + (size_t)v1;
    int v2 = is64 ? (int)((const long long*)re2)[j] : ((const int*)re2)[j];
    g_comp[idx] = v2;
}

// ---------------------------------------------------------------------------
// Persistent fused block kernel with work stealing.
// gather (indexed or linear, prefetched) -> conv x3 (TMEM) -> residual -> scatter
// ---------------------------------------------------------------------------
__global__ __launch_bounds__(NTHREADS, 1)
void block_kernel(const float* __restrict__ xin, float* __restrict__ xout,
                  const void* __restrict__ gIdx, int linearGather,
                  const void* __restrict__ scIdx, int scMode,
                  const float* __restrict__ wslab, const float* __restrict__ bias,
                  int* __restrict__ ctr) {
    extern __shared__ char smem[];
    const int tid  = threadIdx.x;
    const int warp = tid >> 5;
    const int lane = tid & 31;
    const int is64  = g_is64;
    const int sIs64 = scMode ? is64 : 0;

    const uint32_t sbase = smem_u32(smem);
    float* sBias = (float*)(smem + OFF_BIAS);
    float* sW    = (float*)(smem + OFF_W);
    int*   sWrk  = (int*)(smem + OFF_WORK);

    const int inOff[2]   = {OFF_IN0, OFF_IN1};
    const int idxGOff[2] = {OFF_IDXG0, OFF_IDXG1};
    const int idxSOff[2] = {OFF_IDXS0, OFF_IDXS1};

#if HAS_TC
    const uint32_t mbar = sbase + OFF_MBAR;
    if (tid == 0) { MBAR_INIT(mbar, 1); MBAR_INIT(mbar + 8, 1); }
    if (warp == 0) {
        TCGEN05_ALLOC(sbase + OFF_TM, 128);
        TCGEN05_RELINQ();
    }
#endif

    // steal first work + bias + layer-0 weights
    if (tid == 0) sWrk[0] = atomicAdd(ctr, 1);
    if (tid < 3 * CH) sBias[tid] = bias[tid];
#pragma unroll
    for (int k = 0; k < 6; k++)
        ((float4*)sW)[tid + k * NTHREADS] = ((const float4*)wslab)[tid + k * NTHREADS];
    __syncthreads();
    int work = sWrk[0];

    // ---- prologue: idx + gather for the first work ----
    if (work < NWORK) {
        int b0 = work / GRID_X, t0 = (work % GRID_X) * TILE;
        int* sG = (int*)(smem + OFF_IDXG0);
        int* sS = (int*)(smem + OFF_IDXS0);
        if (!linearGather) {
            for (int r = tid; r < R_IN; r += NTHREADS) {
                int p = t0 - 3 + r;
                int v = -1;
                if (p >= 0 && p < NPTS) {
                    size_t gp = (size_t)b0 * NPTS + p;
                    v = is64 ? (int)((const long long*)gIdx)[gp] : ((const int*)gIdx)[gp];
                }
                sG[r] = v;
            }
        }
        for (int r = tid; r < TILE; r += NTHREADS) {
            int p = t0 + r;
            int v = 0;
            if (p < NPTS) {
                size_t gp = (size_t)b0 * NPTS + p;
                v = sIs64 ? (int)((const long long*)scIdx)[gp] : ((const int*)scIdx)[gp];
            }
            sS[r] = v;
        }
        __syncthreads();
        const float* xb = xin + (size_t)b0 * NPTS * CH;
        for (int it = tid; it < R_IN * 16; it += NTHREADS) {
            int r = it >> 4, c = it & 15;
            if (!linearGather) {
                int src = sG[r];
                cp16(sbase + OFF_IN0 + (uint32_t)(c * R_IN + r) * 16,
                     (src >= 0) ? (const void*)(xb + (size_t)src * CH + c * 4) : (const void*)xin,
                     src >= 0);
            } else {
                int p = t0 - 3 + r;
                int valid = (p >= 0) && (p < NPTS);
                int pc = valid ? p : 0;
                cp16(sbase + OFF_IN0 + (uint32_t)(c * R_IN + r) * 16,
                     (const void*)(xb + (size_t)pc * CH + c * 4), valid);
            }
        }
    }
    CP_COMMIT();

#if HAS_TC
    uint32_t tmem;
    asm volatile("ld.shared.b32 %0, [%1];" : "=r"(tmem) : "r"(sbase + OFF_TM));

    // Warp mapping: tile = w>>3, colhalf = (w>>2)&1, subpartition = w&3
    const int mtile = warp >> 3;
    const int colh  = (warp >> 2) & 1;
    const int myrow = mtile * 128 + (warp & 3) * 32 + lane;
    const uint32_t dcol   = tmem + mtile * 64 + colh * 32;
    const uint32_t mymbar = mbar + mtile * 8;
    const uint32_t otmbar = mbar + (1 - mtile) * 8;

    int ph = 0;
    int cur = 0;
    while (work < NWORK) {
        const int b     = work / GRID_X;
        const int tile0 = (work % GRID_X) * TILE;
        const int nxt   = cur ^ 1;
        const uint32_t IN = sbase + inOff[cur];
        char* INp = smem + inOff[cur];
        int* sG_n = (int*)(smem + idxGOff[nxt]);
        int* sS_c = (int*)(smem + idxSOff[cur]);
        int* sS_n = (int*)(smem + idxSOff[nxt]);

        if (tid == 0) sWrk[0] = atomicAdd(ctr, 1);   // steal next work
        CP_WAIT0();
        TCGEN05_FENCE_BEFORE();
        FENCE_ASYNC();
        __syncthreads();
        const int wnext = sWrk[0];

        // ======== conv1: IN -> TMEM -> B1 ========
        if (warp == 0 && elect_one())
            issue_conv(IN, R_IN, sbase + OFF_W, tmem, mbar);

        // under the MMA: load next tile's indices + prefetch W1
        if (wnext < NWORK) {
            int bn = wnext / GRID_X, tn = (wnext % GRID_X) * TILE;
            if (!linearGather) {
                for (int r = tid; r < R_IN; r += NTHREADS) {
                    int p = tn - 3 + r;
                    int v = -1;
                    if (p >= 0 && p < NPTS) {
                        size_t gp = (size_t)bn * NPTS + p;
                        v = is64 ? (int)((const long long*)gIdx)[gp] : ((const int*)gIdx)[gp];
                    }
                    sG_n[r] = v;
                }
            }
            for (int r = tid; r < TILE; r += NTHREADS) {
                int p = tn + r;
                int v = 0;
                if (p < NPTS) {
                    size_t gp = (size_t)bn * NPTS + p;
                    v = sIs64 ? (int)((const long long*)scIdx)[gp] : ((const int*)scIdx)[gp];
                }
                sS_n[r] = v;
            }
        }
        float4 wreg[6];
#pragma unroll
        for (int k = 0; k < 6; k++) wreg[k] = ((const float4*)(wslab + 12288))[tid + k * NTHREADS];

        MBAR_WAIT(mymbar, ph);
        TCGEN05_FENCE_AFTER();
        {
            uint32_t rg[32];
            LDTM_X32(rg, dcol);
            TCGEN05_WAIT_LD();
            int r = myrow, p = tile0 - 2 + r;
            if (r < R_B1) {
                bool zero = (p < 0) || (p >= NPTS);
#pragma unroll
                for (int j = 0; j < 8; j++) {
                    int c = colh * 8 + j;
                    float4 v = make_float4(0.f, 0.f, 0.f, 0.f);
                    if (!zero) {
                        float4 bb = *(const float4*)(sBias + c * 4);
                        v.x = fmaxf(__uint_as_float(rg[j * 4 + 0]) + bb.x, 0.f);
                        v.y = fmaxf(__uint_as_float(rg[j * 4 + 1]) + bb.y, 0.f);
                        v.z = fmaxf(__uint_as_float(rg[j * 4 + 2]) + bb.z, 0.f);
                        v.w = fmaxf(__uint_as_float(rg[j * 4 + 3]) + bb.w, 0.f);
                    }
                    *(float4*)(smem + OFF_B1 + ((size_t)c * R_B1 + r) * 16) = v;
                }
            }
        }
        MBAR_WAIT(otmbar, ph);     // both tiles done with sW
#pragma unroll
        for (int k = 0; k < 6; k++) ((float4*)sW)[tid + k * NTHREADS] = wreg[k];
        ph ^= 1;
        TCGEN05_FENCE_BEFORE();
        FENCE_ASYNC();
        __syncthreads();

        // ======== conv2: B1 -> TMEM; epilogue writes B2 back into B1 buffer ========
        if (warp == 0 && elect_one())
            issue_conv(sbase + OFF_B1, R_B1, sbase + OFF_W, tmem, mbar);

        // under the MMA: issue next tile's gather + prefetch W2
        if (wnext < NWORK) {
            int bn = wnext / GRID_X, tn = (wnext % GRID_X) * TILE;
            const float* xb = xin + (size_t)bn * NPTS * CH;
            for (int it = tid; it < R_IN * 16; it += NTHREADS) {
                int r = it >> 4, c = it & 15;
                if (!linearGather) {
                    int src = sG_n[r];
                    cp16(sbase + inOff[nxt] + (uint32_t)(c * R_IN + r) * 16,
                         (src >= 0) ? (const void*)(xb + (size_t)src * CH + c * 4) : (const void*)xin,
                         src >= 0);
                } else {
                    int p = tn - 3 + r;
                    int valid = (p >= 0) && (p < NPTS);
                    int pc = valid ? p : 0;
                    cp16(sbase + inOff[nxt] + (uint32_t)(c * R_IN + r) * 16,
                         (const void*)(xb + (size_t)pc * CH + c * 4), valid);
                }
            }
        }
        CP_COMMIT();
#pragma unroll
        for (int k = 0; k < 6; k++) wreg[k] = ((const float4*)(wslab + 24576))[tid + k * NTHREADS];

        MBAR_WAIT(mymbar, ph);
        TCGEN05_FENCE_AFTER();
        uint32_t rg2[32];
        LDTM_X32(rg2, dcol);
        TCGEN05_WAIT_LD();
        MBAR_WAIT(otmbar, ph);     // ALL conv2 MMAs done reading B1 -> safe to overwrite
        ph ^= 1;
        {
            int r = myrow, p = tile0 - 1 + r;
            if (r < R_B2) {
                bool zero = (p < 0) || (p >= NPTS);
#pragma unroll
                for (int j = 0; j < 8; j++) {
                    int c = colh * 8 + j;
                    float4 v = make_float4(0.f, 0.f, 0.f, 0.f);
                    if (!zero) {
                        float4 bb = *(const float4*)(sBias + 64 + c * 4);
                        v.x = fmaxf(__uint_as_float(rg2[j * 4 + 0]) + bb.x, 0.f);
                        v.y = fmaxf(__uint_as_float(rg2[j * 4 + 1]) + bb.y, 0.f);
                        v.z = fmaxf(__uint_as_float(rg2[j * 4 + 2]) + bb.z, 0.f);
                        v.w = fmaxf(__uint_as_float(rg2[j * 4 + 3]) + bb.w, 0.f);
                    }
                    *(float4*)(smem + OFF_B1 + ((size_t)c * R_B2 + r) * 16) = v;
                }
            }
        }
#pragma unroll
        for (int k = 0; k < 6; k++) ((float4*)sW)[tid + k * NTHREADS] = wreg[k];
        TCGEN05_FENCE_BEFORE();
        FENCE_ASYNC();
        __syncthreads();

        // ======== conv3: B1 (B2 layout) -> TMEM ========
        if (warp == 0 && elect_one())
            issue_conv(sbase + OFF_B1, R_B2, sbase + OFF_W, tmem, mbar);

        // prefetch next tile's W0 under the MMA
#pragma unroll
        for (int k = 0; k < 6; k++) wreg[k] = ((const float4*)wslab)[tid + k * NTHREADS];

        MBAR_WAIT(mymbar, ph);
        TCGEN05_FENCE_AFTER();
        {
            uint32_t rg[32];
            LDTM_X32(rg, dcol);
            TCGEN05_WAIT_LD();
            int r = myrow;
            bool go = (r < TILE) && (tile0 + r < NPTS);
            if (go) {
                int dst = sS_c[r];
                float* outp = xout + ((size_t)b * NPTS + dst) * CH;
#pragma unroll
                for (int j = 0; j < 8; j++) {
                    int c = colh * 8 + j;
                    float4 res = *(const float4*)(INp + ((size_t)c * R_IN + (r + 3)) * 16);
                    float4 bb  = *(const float4*)(sBias + 128 + c * 4);
                    float4 y;
                    y.x = fmaxf(res.x + __uint_as_float(rg[j * 4 + 0]) + bb.x, 0.f);
                    y.y = fmaxf(res.y + __uint_as_float(rg[j * 4 + 1]) + bb.y, 0.f);
                    y.z = fmaxf(res.z + __uint_as_float(rg[j * 4 + 2]) + bb.z, 0.f);
                    y.w = fmaxf(res.w + __uint_as_float(rg[j * 4 + 3]) + bb.w, 0.f);
                    *(float4*)(outp + c * 4) = y;
                }
            }
        }
        MBAR_WAIT(otmbar, ph);
        ph ^= 1;
#pragma unroll
        for (int k = 0; k < 6; k++) ((float4*)sW)[tid + k * NTHREADS] = wreg[k];
        TCGEN05_FENCE_BEFORE();
        __syncthreads();

        work = wnext;
        cur ^= 1;
    }
    if (warp == 0) TCGEN05_DEALLOC(tmem, 128);

#else // ---- scalar fallback (compute_103 JIT image only): static striding ----
    CP_WAIT0();
    __syncthreads();
    for (int w2 = blockIdx.x; w2 < NWORK; w2 += gridDim.x) {
        const int b     = w2 / GRID_X;
        const int tile0 = (w2 % GRID_X) * TILE;
        int* sG = (int*)(smem + OFF_IDXG0);
        int* sS = (int*)(smem + OFF_IDXS0);
        __syncthreads();
        if (!linearGather) {
            for (int r = tid; r < R_IN; r += NTHREADS) {
                int p = tile0 - 3 + r;
                int v = -1;
                if (p >= 0 && p < NPTS) {
                    size_t gp = (size_t)b * NPTS + p;
                    v = is64 ? (int)((const long long*)gIdx)[gp] : ((const int*)gIdx)[gp];
                }
                sG[r] = v;
            }
        }
        for (int r = tid; r < TILE; r += NTHREADS) {
            int p = tile0 + r;
            int v = 0;
            if (p < NPTS) {
                size_t gp = (size_t)b * NPTS + p;
                v = sIs64 ? (int)((const long long*)scIdx)[gp] : ((const int*)scIdx)[gp];
            }
            sS[r] = v;
        }
        __syncthreads();
        const float* xb = xin + (size_t)b * NPTS * CH;
        for (int it = tid; it < R_IN * 16; it += NTHREADS) {
            int r = it >> 4, c = it & 15;
            float4 v = make_float4(0.f, 0.f, 0.f, 0.f);
            if (!linearGather) {
                int src = sG[r];
                if (src >= 0) v = *(const float4*)(xb + (size_t)src * CH + c * 4);
            } else {
                int p = tile0 - 3 + r;
                if (p >= 0 && p < NPTS) v = *(const float4*)(xb + (size_t)p * CH + c * 4);
            }
            *(float4*)(smem + OFF_IN0 + ((size_t)c * R_IN + r) * 16) = v;
        }
        __syncthreads();
        conv_scalar(smem, OFF_IN0, R_IN, OFF_B1, R_B1, R_B1, tile0 - 2, sW, sBias, tid);
        __syncthreads();
        for (int it = tid; it < 3072; it += NTHREADS)
            ((float4*)sW)[it] = ((const float4*)(wslab + 12288))[it];
        __syncthreads();
        conv_scalar(smem, OFF_B1, R_B1, OFF_IN1, R_B2, R_B2, tile0 - 1, sW, sBias + 64, tid);
        __syncthreads();
        for (int it = tid; it < 3072; it += NTHREADS)
            ((float4*)sW)[it] = ((const float4*)(wslab + 24576))[it];
        __syncthreads();
        conv_scalar(smem, OFF_IN1, R_B2, OFF_B1, R_B1, TILE, tile0, sW, nullptr, tid);
        __syncthreads();
        for (int it = tid; it < TILE * 16; it += NTHREADS) {
            int r = it >> 4, c = it & 15;
            if (tile0 + r >= NPTS) continue;
            int dst = sS[r];
            float4 h   = *(const float4*)(smem + OFF_B1 + ((size_t)c * R_B1 + r) * 16);
            float4 res = *(const float4*)(smem + OFF_IN0 + ((size_t)c * R_IN + (r + 3)) * 16);
            float4 bb  = *(const float4*)(sBias + 128 + c * 4);
            float4 y;
            y.x = fmaxf(res.x + h.x + bb.x, 0.f);
            y.y = fmaxf(res.y + h.y + bb.y, 0.f);
            y.z = fmaxf(res.z + h.z + bb.z, 0.f);
            y.w = fmaxf(res.w + h.w + bb.w, 0.f);
            *(float4*)(xout + ((size_t)b * NPTS + dst) * CH + c * 4) = y;
        }
        __syncthreads();
        for (int it = tid; it < 3072; it += NTHREADS)
            ((float4*)sW)[it] = ((const float4*)wslab)[it];
        __syncthreads();
    }
#endif
}

// ---------------------------------------------------------------------------
// Launch
// ---------------------------------------------------------------------------
extern "C" void kernel_launch(void* const* d_in, const int* in_sizes, int n_in,
                              void* d_out, int out_size) {
    const float* x      = (const float*)d_in[0];
    const void*  pa1    = d_in[1];
    const void*  pa2    = d_in[3];
    const void*  re2    = d_in[4];
    const float* conv_w = (const float*)d_in[5];
    const float* gma    = (const float*)d_in[6];
    const float* bta    = (const float*)d_in[7];
    const float* mean   = (const float*)d_in[8];
    const float* var    = (const float*)d_in[9];

    float* mid;  cudaGetSymbolAddress((void**)&mid,  g_mid);
    float* wt2;  cudaGetSymbolAddress((void**)&wt2,  g_wt2);
    float* bias; cudaGetSymbolAddress((void**)&bias, g_bias);
    int*   comp; cudaGetSymbolAddress((void**)&comp, g_comp);
    int*   ctr;  cudaGetSymbolAddress((void**)&ctr,  g_ctr);

    int nsm = 148;
    cudaDeviceGetAttribute(&nsm, cudaDevAttrMultiProcessorCount, 0);

    cudaFuncSetAttribute(block_kernel, cudaFuncAttributeMaxDynamicSharedMemorySize, SMEM_BYTES);

    detect_idx_kernel<<<1, 256>>>((const unsigned int*)pa1);
    repack_kernel<<<(NBLK * 3 * CH * CH + 255) / 256, 256>>>(conv_w, gma, bta, mean, var);
    compose_kernel<<<(NBATCH * NPTS + 255) / 256, 256>>>(pa1, re2);

    // block 1: x --(gather pa1)--> conv --(scatter comp)--> mid (block2-gather order)
    block_kernel<<<nsm, NTHREADS, SMEM_BYTES>>>(x, mid, pa1, 0, comp, 0, wt2, bias, ctr);
    // block 2: mid --(linear gather)--> conv --(scatter pa2)--> out
    block_kernel<<<nsm, NTHREADS, SMEM_BYTES>>>(mid, (float*)d_out, nullptr, 1,
                                                pa2, 1, wt2 + 3 * 12288, bias + 3 * CH,
                                                ctr + 1);
}